// round 2
// baseline (speedup 1.0000x reference)
#include <cuda_runtime.h>
#include <math.h>

#define BB 4
#define TT 1024
#define DD 1024
#define HH 16
#define DHH 64
#define DCC 64
#define BT (BB*TT)        // 4096
#define BTD (BB*TT*DD)    // 4194304
#define BIAS_ELEMS (HH*TT*TT) // 16777216

// ---------------- scratch (device globals; no allocation) ----------------
__device__ float g_gamma1[BB*DD];
__device__ float g_beta1 [BB*DD];
__device__ float g_gamma3[BB*DD];
__device__ float g_beta3 [BB*DD];
__device__ float g_y   [BTD];           // normed+film activations (reused)
__device__ float g_q   [BTD];
__device__ float g_k   [BTD];
__device__ float g_v   [BTD];
__device__ float g_ctx [BTD];           // attention context before wo
__device__ float g_x1  [BTD];           // residual after attention
__device__ float g_bias[BIAS_ELEMS];    // [H,T,T]
__device__ float g_attn[(size_t)BB*HH*TT*TT]; // 256 MB scores/probs
__device__ float g_ffn1[(size_t)BT*4*DD];     // 4096 x 4096
__device__ float g_gg  [(size_t)BT*2*DD];     // geglu output

// ---------------- FiLM params: gamma/beta = cond @ W + b ----------------
__global__ void film_params_kernel(const float* __restrict__ cond,
    const float* __restrict__ g1w, const float* __restrict__ g1b,
    const float* __restrict__ b1w, const float* __restrict__ b1b,
    const float* __restrict__ g3w, const float* __restrict__ g3b,
    const float* __restrict__ b3w, const float* __restrict__ b3b)
{
    int idx = blockIdx.x * blockDim.x + threadIdx.x;
    if (idx >= BB*DD) return;
    int b = idx / DD, d = idx % DD;
    float s1 = 0.f, s2 = 0.f, s3 = 0.f, s4 = 0.f;
    #pragma unroll 8
    for (int c = 0; c < DCC; c++) {
        float cv = cond[b*DCC + c];
        s1 += cv * g1w[c*DD + d];
        s2 += cv * b1w[c*DD + d];
        s3 += cv * g3w[c*DD + d];
        s4 += cv * b3w[c*DD + d];
    }
    g_gamma1[idx] = s1 + g1b[d];
    g_beta1 [idx] = s2 + b1b[d];
    g_gamma3[idx] = s3 + g3b[d];
    g_beta3 [idx] = s4 + b3b[d];
}

// ---------------- T5 relative position bias ----------------
__global__ void bias_kernel(const float* __restrict__ rel_emb, float* __restrict__ outbias)
{
    int idx = blockIdx.x * blockDim.x + threadIdx.x; // over T*T
    if (idx >= TT*TT) return;
    int q = idx / TT, k = idx % TT;
    int rp = k - q;                 // kpos - qpos
    int bucket = (rp > 0) ? 16 : 0;
    int arp = rp < 0 ? -rp : rp;
    int off;
    if (arp < 8) {
        off = arp;
    } else {
        float l = logf((float)arp * 0.125f) / logf(16.0f) * 8.0f;
        off = 8 + (int)l;          // truncation matches astype(int32)
        if (off > 15) off = 15;
    }
    bucket += off;
    #pragma unroll
    for (int h = 0; h < HH; h++) {
        float v = rel_emb[bucket*HH + h];
        g_bias[(size_t)h*TT*TT + idx] = v;
        if (outbias) outbias[(size_t)h*TT*TT + idx] = v;
    }
}

// ---------------- RMSNorm + FiLM ----------------
__global__ void rmsnorm_film_kernel(const float* __restrict__ x, const float* __restrict__ w,
                                    const float* __restrict__ gamma, const float* __restrict__ beta,
                                    float* __restrict__ y)
{
    int row = blockIdx.x;               // 0..BT-1
    int b = row / TT;
    const float* xr = x + (size_t)row * DD;
    float* yr = y + (size_t)row * DD;
    __shared__ float red[256];
    float s = 0.f;
    for (int d = threadIdx.x; d < DD; d += 256) { float v = xr[d]; s += v*v; }
    red[threadIdx.x] = s; __syncthreads();
    for (int o = 128; o > 0; o >>= 1) {
        if (threadIdx.x < o) red[threadIdx.x] += red[threadIdx.x + o];
        __syncthreads();
    }
    float rs = rsqrtf(red[0] * (1.0f/DD) + 1e-6f);
    for (int d = threadIdx.x; d < DD; d += 256) {
        float v = w[d] * xr[d] * rs;
        yr[d] = v * (gamma[b*DD + d] + 1.0f) + beta[b*DD + d];
    }
}

// ---------------- SGEMM 128x128x8, optional residual ----------------
// C[M,N] = A[M,K] @ B[K,N] (+ Res). M%128==0, N%128==0, K%8==0.
__global__ __launch_bounds__(256) void sgemm_kernel(int M, int N, int K,
    const float* __restrict__ A, const float* __restrict__ Bm,
    const float* __restrict__ Res, float* __restrict__ C)
{
    const int BM = 128, BN = 128, BK = 8, TM = 8, TN = 8;
    __shared__ float As[BK][BM];
    __shared__ float Bs[BK][BN];
    int tid = threadIdx.x;
    int bx = blockIdx.x, by = blockIdx.y;
    A  += (size_t)by * BM * K;
    Bm += bx * BN;
    C  += (size_t)by * BM * N + bx * BN;
    if (Res) Res += (size_t)by * BM * N + bx * BN;

    int arow = tid >> 1, acol = (tid & 1) * 4;
    int brow = tid >> 5, bcol = (tid & 31) * 4;
    int ty = tid >> 4, tx = tid & 15;

    float acc[TM][TN];
    #pragma unroll
    for (int i = 0; i < TM; i++)
        #pragma unroll
        for (int j = 0; j < TN; j++) acc[i][j] = 0.f;

    for (int kt = 0; kt < K; kt += BK) {
        float4 a4 = *reinterpret_cast<const float4*>(&A[(size_t)arow * K + kt + acol]);
        As[acol+0][arow] = a4.x; As[acol+1][arow] = a4.y;
        As[acol+2][arow] = a4.z; As[acol+3][arow] = a4.w;
        float4 b4 = *reinterpret_cast<const float4*>(&Bm[(size_t)(kt + brow) * N + bcol]);
        *reinterpret_cast<float4*>(&Bs[brow][bcol]) = b4;
        __syncthreads();
        #pragma unroll
        for (int k = 0; k < BK; k++) {
            float regM[TM], regN[TN];
            #pragma unroll
            for (int i = 0; i < TM; i++) regM[i] = As[k][ty*TM + i];
            #pragma unroll
            for (int j = 0; j < TN; j++) regN[j] = Bs[k][tx*TN + j];
            #pragma unroll
            for (int i = 0; i < TM; i++)
                #pragma unroll
                for (int j = 0; j < TN; j++) acc[i][j] += regM[i] * regN[j];
        }
        __syncthreads();
    }
    #pragma unroll
    for (int i = 0; i < TM; i++) {
        int r = ty*TM + i;
        #pragma unroll
        for (int j = 0; j < TN; j++) {
            int c = tx*TN + j;
            float v = acc[i][j];
            if (Res) v += Res[(size_t)r * N + c];
            C[(size_t)r * N + c] = v;
        }
    }
}

// ---------------- scores: S = Q Kᵀ / sqrt(DH) + bias, masked ----------------
__global__ __launch_bounds__(256) void scores_kernel(const int* __restrict__ mask)
{
    __shared__ float Qs[64][65];
    __shared__ float Ks[64][65];
    int b = blockIdx.z / HH, h = blockIdx.z % HH;
    int q0 = blockIdx.y * 64, k0 = blockIdx.x * 64;
    int tid = threadIdx.x;

    #pragma unroll
    for (int i = 0; i < 16; i++) {
        int idx = tid + i * 256;
        int r = idx >> 6, c = idx & 63;
        Qs[r][c] = g_q[(size_t)(b*TT + q0 + r) * DD + h*DHH + c];
        Ks[r][c] = g_k[(size_t)(b*TT + k0 + r) * DD + h*DHH + c];
    }
    __syncthreads();

    int ty = tid >> 4, tx = tid & 15;
    float acc[4][4];
    #pragma unroll
    for (int i = 0; i < 4; i++)
        #pragma unroll
        for (int j = 0; j < 4; j++) acc[i][j] = 0.f;

    #pragma unroll 8
    for (int kk = 0; kk < 64; kk++) {
        float rq[4], rk[4];
        #pragma unroll
        for (int i = 0; i < 4; i++) rq[i] = Qs[ty*4 + i][kk];
        #pragma unroll
        for (int j = 0; j < 4; j++) rk[j] = Ks[tx*4 + j][kk];
        #pragma unroll
        for (int i = 0; i < 4; i++)
            #pragma unroll
            for (int j = 0; j < 4; j++) acc[i][j] += rq[i] * rk[j];
    }

    #pragma unroll
    for (int i = 0; i < 4; i++) {
        int q = q0 + ty*4 + i;
        #pragma unroll
        for (int j = 0; j < 4; j++) {
            int k = k0 + tx*4 + j;
            float s = acc[i][j] * 0.125f + g_bias[(size_t)h*TT*TT + (size_t)q*TT + k];
            if (mask[(size_t)b*TT*TT + (size_t)q*TT + k] == 0) s = -1e9f;
            g_attn[(((size_t)(b*HH + h))*TT + q)*TT + k] = s;
        }
    }
}

// ---------------- softmax over last dim ----------------
__global__ void softmax_kernel()
{
    size_t row = blockIdx.x; // B*H*T rows
    float* p = g_attn + row * TT;
    __shared__ float red[256];
    float m = -1e30f;
    for (int i = threadIdx.x; i < TT; i += 256) m = fmaxf(m, p[i]);
    red[threadIdx.x] = m; __syncthreads();
    for (int o = 128; o > 0; o >>= 1) {
        if (threadIdx.x < o) red[threadIdx.x] = fmaxf(red[threadIdx.x], red[threadIdx.x + o]);
        __syncthreads();
    }
    m = red[0];
    __syncthreads();
    float s = 0.f;
    for (int i = threadIdx.x; i < TT; i += 256) {
        float e = __expf(p[i] - m);
        p[i] = e;
        s += e;
    }
    red[threadIdx.x] = s; __syncthreads();
    for (int o = 128; o > 0; o >>= 1) {
        if (threadIdx.x < o) red[threadIdx.x] += red[threadIdx.x + o];
        __syncthreads();
    }
    float inv = 1.0f / red[0];
    for (int i = threadIdx.x; i < TT; i += 256) p[i] *= inv;
}

// ---------------- ctx = P @ V ----------------
__global__ __launch_bounds__(256) void attnv_kernel()
{
    __shared__ float Ps[64][65];
    __shared__ float Vs[64][65];
    int b = blockIdx.y / HH, h = blockIdx.y % HH;
    int q0 = blockIdx.x * 64;
    int tid = threadIdx.x;
    int ty = tid >> 4, tx = tid & 15;

    float acc[4][4];
    #pragma unroll
    for (int i = 0; i < 4; i++)
        #pragma unroll
        for (int j = 0; j < 4; j++) acc[i][j] = 0.f;

    for (int kt = 0; kt < TT; kt += 64) {
        #pragma unroll
        for (int i = 0; i < 16; i++) {
            int idx = tid + i * 256;
            int r = idx >> 6, c = idx & 63;
            Ps[r][c] = g_attn[(((size_t)(b*HH + h))*TT + q0 + r)*TT + kt + c];
            Vs[r][c] = g_v[(size_t)(b*TT + kt + r) * DD + h*DHH + c];
        }
        __syncthreads();
        #pragma unroll 8
        for (int kk = 0; kk < 64; kk++) {
            float rp[4], rv[4];
            #pragma unroll
            for (int i = 0; i < 4; i++) rp[i] = Ps[ty*4 + i][kk];
            #pragma unroll
            for (int j = 0; j < 4; j++) rv[j] = Vs[kk][tx*4 + j];
            #pragma unroll
            for (int i = 0; i < 4; i++)
                #pragma unroll
                for (int j = 0; j < 4; j++) acc[i][j] += rp[i] * rv[j];
        }
        __syncthreads();
    }
    #pragma unroll
    for (int i = 0; i < 4; i++)
        #pragma unroll
        for (int j = 0; j < 4; j++)
            g_ctx[(size_t)(b*TT + q0 + ty*4 + i) * DD + h*DHH + tx*4 + j] = acc[i][j];
}

// ---------------- GEGLU: p1 * gelu_exact(p2) ----------------
__global__ void geglu_kernel()
{
    size_t idx = (size_t)blockIdx.x * blockDim.x + threadIdx.x; // over BT*2D
    if (idx >= (size_t)BT * 2 * DD) return;
    size_t r = idx / (2*DD);
    int c = (int)(idx % (2*DD));
    float p1 = g_ffn1[r * 4*DD + c];
    float p2 = g_ffn1[r * 4*DD + 2*DD + c];
    float gelu = 0.5f * p2 * (1.0f + erff(p2 * 0.70710678118654752f));
    g_gg[idx] = p1 * gelu;
}

// ---------------- host launcher ----------------
extern "C" void kernel_launch(void* const* d_in, const int* in_sizes, int n_in,
                              void* d_out, int out_size)
{
    const float* x       = (const float*)d_in[0];
    const int*   mask    = (const int*)  d_in[1];
    const float* cond    = (const float*)d_in[2];
    const float* norm1_w = (const float*)d_in[3];
    const float* f1gw    = (const float*)d_in[4];
    const float* f1gb    = (const float*)d_in[5];
    const float* f1bw    = (const float*)d_in[6];
    const float* f1bb    = (const float*)d_in[7];
    const float* wq      = (const float*)d_in[8];
    const float* wk      = (const float*)d_in[9];
    const float* wv      = (const float*)d_in[10];
    const float* wo      = (const float*)d_in[11];
    const float* rel_emb = (const float*)d_in[12];
    const float* norm3_w = (const float*)d_in[13];
    const float* f3gw    = (const float*)d_in[14];
    const float* f3gb    = (const float*)d_in[15];
    const float* f3bw    = (const float*)d_in[16];
    const float* f3bb    = (const float*)d_in[17];
    const float* w1      = (const float*)d_in[18];
    const float* w2      = (const float*)d_in[19];
    float* out = (float*)d_out;
    float* outbias = (out_size >= BTD + BIAS_ELEMS) ? out + BTD : nullptr;

    // resolve scratch symbol addresses (non-stream API, capture-safe)
    float *p_g1, *p_b1, *p_g3, *p_b3, *p_y, *p_q, *p_k, *p_v, *p_ctx, *p_x1, *p_ffn1, *p_gg;
    cudaGetSymbolAddress((void**)&p_g1, g_gamma1);
    cudaGetSymbolAddress((void**)&p_b1, g_beta1);
    cudaGetSymbolAddress((void**)&p_g3, g_gamma3);
    cudaGetSymbolAddress((void**)&p_b3, g_beta3);
    cudaGetSymbolAddress((void**)&p_y,  g_y);
    cudaGetSymbolAddress((void**)&p_q,  g_q);
    cudaGetSymbolAddress((void**)&p_k,  g_k);
    cudaGetSymbolAddress((void**)&p_v,  g_v);
    cudaGetSymbolAddress((void**)&p_ctx, g_ctx);
    cudaGetSymbolAddress((void**)&p_x1, g_x1);
    cudaGetSymbolAddress((void**)&p_ffn1, g_ffn1);
    cudaGetSymbolAddress((void**)&p_gg, g_gg);

    // 1) FiLM parameters + position bias (independent)
    film_params_kernel<<<(BB*DD + 255)/256, 256>>>(cond, f1gw, f1gb, f1bw, f1bb,
                                                   f3gw, f3gb, f3bw, f3bb);
    bias_kernel<<<(TT*TT + 255)/256, 256>>>(rel_emb, outbias);

    // 2) y = film(rmsnorm(x))
    rmsnorm_film_kernel<<<BT, 256>>>(x, norm1_w, p_g1, p_b1, p_y);

    // 3) Q/K/V projections
    dim3 gproj(DD/128, BT/128);
    sgemm_kernel<<<gproj, 256>>>(BT, DD, DD, p_y, wq, nullptr, p_q);
    sgemm_kernel<<<gproj, 256>>>(BT, DD, DD, p_y, wk, nullptr, p_k);
    sgemm_kernel<<<gproj, 256>>>(BT, DD, DD, p_y, wv, nullptr, p_v);

    // 4) attention
    scores_kernel<<<dim3(TT/64, TT/64, BB*HH), 256>>>(mask);
    softmax_kernel<<<BB*HH*TT, 256>>>();
    attnv_kernel<<<dim3(TT/64, BB*HH), 256>>>();

    // 5) output projection + residual -> x1
    sgemm_kernel<<<gproj, 256>>>(BT, DD, DD, p_ctx, wo, x, p_x1);

    // 6) y2 = film3(rmsnorm(x1))
    rmsnorm_film_kernel<<<BT, 256>>>(p_x1, norm3_w, p_g3, p_b3, p_y);

    // 7) FFN: h = y2 @ w1 ; gg = geglu(h) ; out = gg @ w2 + x1
    sgemm_kernel<<<dim3(4*DD/128, BT/128), 256>>>(BT, 4*DD, DD, p_y, w1, nullptr, p_ffn1);
    geglu_kernel<<<(int)(((size_t)BT*2*DD + 255)/256), 256>>>();
    sgemm_kernel<<<dim3(DD/128, BT/128), 256>>>(BT, DD, 2*DD, p_gg, w2, p_x1, out);
}

// round 5
// speedup vs baseline: 1.8522x; 1.8522x over previous
#include <cuda_runtime.h>
#include <math.h>

#define BB 4
#define TT 1024
#define DD 1024
#define HH 16
#define DHH 64
#define DCC 64
#define BT (BB*TT)        // 4096
#define BTD (BB*TT*DD)    // 4194304
#define BIAS_ELEMS (HH*TT*TT) // 16777216

// ---------------- scratch (device globals; no allocation) ----------------
__device__ float g_gamma1[BB*DD];
__device__ float g_beta1 [BB*DD];
__device__ float g_gamma3[BB*DD];
__device__ float g_beta3 [BB*DD];
__device__ float g_y   [BTD];
__device__ float g_q   [BTD];
__device__ float g_k   [BTD];
__device__ float g_v   [BTD];
__device__ float g_ctx [BTD];
__device__ float g_x1  [BTD];
__device__ float g_bias[BIAS_ELEMS];
__device__ float g_attn[(size_t)BB*HH*TT*TT];
__device__ float g_ffn1[(size_t)BT*4*DD];
__device__ float g_gg  [(size_t)BT*2*DD];

// ---------------- FiLM params ----------------
__global__ void film_params_kernel(const float* __restrict__ cond,
    const float* __restrict__ g1w, const float* __restrict__ g1b,
    const float* __restrict__ b1w, const float* __restrict__ b1b,
    const float* __restrict__ g3w, const float* __restrict__ g3b,
    const float* __restrict__ b3w, const float* __restrict__ b3b)
{
    int idx = blockIdx.x * blockDim.x + threadIdx.x;
    if (idx >= BB*DD) return;
    int b = idx / DD, d = idx % DD;
    float s1 = 0.f, s2 = 0.f, s3 = 0.f, s4 = 0.f;
    #pragma unroll 8
    for (int c = 0; c < DCC; c++) {
        float cv = cond[b*DCC + c];
        s1 += cv * g1w[c*DD + d];
        s2 += cv * b1w[c*DD + d];
        s3 += cv * g3w[c*DD + d];
        s4 += cv * b3w[c*DD + d];
    }
    g_gamma1[idx] = s1 + g1b[d];
    g_beta1 [idx] = s2 + b1b[d];
    g_gamma3[idx] = s3 + g3b[d];
    g_beta3 [idx] = s4 + b3b[d];
}

// ---------------- T5 relative position bias ----------------
__global__ void bias_kernel(const float* __restrict__ rel_emb, float* __restrict__ outbias)
{
    int idx = blockIdx.x * blockDim.x + threadIdx.x;
    if (idx >= TT*TT) return;
    int q = idx / TT, k = idx % TT;
    int rp = k - q;
    int bucket = (rp > 0) ? 16 : 0;
    int arp = rp < 0 ? -rp : rp;
    int off;
    if (arp < 8) {
        off = arp;
    } else {
        float l = logf((float)arp * 0.125f) / logf(16.0f) * 8.0f;
        off = 8 + (int)l;
        if (off > 15) off = 15;
    }
    bucket += off;
    #pragma unroll
    for (int h = 0; h < HH; h++) {
        float v = rel_emb[bucket*HH + h];
        g_bias[(size_t)h*TT*TT + idx] = v;
        if (outbias) outbias[(size_t)h*TT*TT + idx] = v;
    }
}

// ---------------- RMSNorm + FiLM ----------------
__global__ void rmsnorm_film_kernel(const float* __restrict__ x, const float* __restrict__ w,
                                    const float* __restrict__ gamma, const float* __restrict__ beta,
                                    float* __restrict__ y)
{
    int row = blockIdx.x;
    int b = row / TT;
    const float* xr = x + (size_t)row * DD;
    float* yr = y + (size_t)row * DD;
    __shared__ float red[256];
    float s = 0.f;
    for (int d = threadIdx.x; d < DD; d += 256) { float v = xr[d]; s += v*v; }
    red[threadIdx.x] = s; __syncthreads();
    for (int o = 128; o > 0; o >>= 1) {
        if (threadIdx.x < o) red[threadIdx.x] += red[threadIdx.x + o];
        __syncthreads();
    }
    float rs = rsqrtf(red[0] * (1.0f/DD) + 1e-6f);
    for (int d = threadIdx.x; d < DD; d += 256) {
        float v = w[d] * xr[d] * rs;
        yr[d] = v * (gamma[b*DD + d] + 1.0f) + beta[b*DD + d];
    }
}

// ---------------- TF32 tensor-core GEMM 128x128x16 ----------------
// C[M,N] = A[M,K] @ B[K,N] (+Res). M%128==0, N%128==0, K%16==0.
#define GBM 128
#define GBN 128
#define GBK 16

__device__ __forceinline__ unsigned smem_u32(const void* p) {
    return (unsigned)__cvta_generic_to_shared(p);
}

__global__ __launch_bounds__(256) void gemm_tf32_kernel(int M, int N, int K,
    const float* __restrict__ A, const float* __restrict__ B,
    const float* __restrict__ Res, float* __restrict__ C)
{
    __shared__ float As[2][GBM][GBK+4];   // +4 pad: ldmatrix conflict-free
    __shared__ float Bs[2][GBK][GBN+8];   // +8 pad: lds B-frag conflict-free

    int tid = threadIdx.x;
    int wid = tid >> 5, lane = tid & 31;
    int wm = wid >> 2, wn = wid & 3;      // warps 2 x 4 -> warp tile 64 x 32

    const float* Ag = A + (size_t)blockIdx.y * GBM * K;
    const float* Bg = B + blockIdx.x * GBN;
    float* Cg = C + (size_t)blockIdx.y * GBM * N + blockIdx.x * GBN;
    const float* Rg = Res ? Res + (size_t)blockIdx.y * GBM * N + blockIdx.x * GBN : nullptr;

    float acc[4][4][4];
    #pragma unroll
    for (int i = 0; i < 4; i++)
        #pragma unroll
        for (int j = 0; j < 4; j++)
            #pragma unroll
            for (int r = 0; r < 4; r++) acc[i][j][r] = 0.f;

    // async loaders: A tile 128x16 (512 float4), B tile 16x128 (512 float4)
    int a_r0 = tid >> 2,       a_c = (tid & 3) * 4;      // +64 rows for second
    int b_r0 = tid >> 5,       b_c = (tid & 31) * 4;     // +8 rows for second

    int nk = K / GBK;
    // prologue: load tile 0
    {
        unsigned d0 = smem_u32(&As[0][a_r0][a_c]);
        unsigned d1 = smem_u32(&As[0][a_r0+64][a_c]);
        asm volatile("cp.async.cg.shared.global [%0], [%1], 16;\n" :: "r"(d0), "l"(Ag + (size_t)a_r0*K + a_c));
        asm volatile("cp.async.cg.shared.global [%0], [%1], 16;\n" :: "r"(d1), "l"(Ag + (size_t)(a_r0+64)*K + a_c));
        unsigned e0 = smem_u32(&Bs[0][b_r0][b_c]);
        unsigned e1 = smem_u32(&Bs[0][b_r0+8][b_c]);
        asm volatile("cp.async.cg.shared.global [%0], [%1], 16;\n" :: "r"(e0), "l"(Bg + (size_t)b_r0*N + b_c));
        asm volatile("cp.async.cg.shared.global [%0], [%1], 16;\n" :: "r"(e1), "l"(Bg + (size_t)(b_r0+8)*N + b_c));
        asm volatile("cp.async.commit_group;\n");
    }

    for (int t = 0; t < nk; t++) {
        if (t + 1 < nk) {
            int nb = (t+1) & 1;
            int kt = (t+1) * GBK;
            unsigned d0 = smem_u32(&As[nb][a_r0][a_c]);
            unsigned d1 = smem_u32(&As[nb][a_r0+64][a_c]);
            asm volatile("cp.async.cg.shared.global [%0], [%1], 16;\n" :: "r"(d0), "l"(Ag + (size_t)a_r0*K + kt + a_c));
            asm volatile("cp.async.cg.shared.global [%0], [%1], 16;\n" :: "r"(d1), "l"(Ag + (size_t)(a_r0+64)*K + kt + a_c));
            unsigned e0 = smem_u32(&Bs[nb][b_r0][b_c]);
            unsigned e1 = smem_u32(&Bs[nb][b_r0+8][b_c]);
            asm volatile("cp.async.cg.shared.global [%0], [%1], 16;\n" :: "r"(e0), "l"(Bg + (size_t)(kt+b_r0)*N + b_c));
            asm volatile("cp.async.cg.shared.global [%0], [%1], 16;\n" :: "r"(e1), "l"(Bg + (size_t)(kt+b_r0+8)*N + b_c));
        }
        asm volatile("cp.async.commit_group;\n");
        asm volatile("cp.async.wait_group 1;\n");
        __syncthreads();

        int buf = t & 1;
        #pragma unroll
        for (int kk = 0; kk < 2; kk++) {
            int k0 = kk * 8;
            unsigned af[4][4];
            unsigned bf[4][2];
            // A fragments via ldmatrix.x4 (submatrices: m/k halves)
            #pragma unroll
            for (int i = 0; i < 4; i++) {
                int m = wm*64 + i*16 + (lane & 7) + ((lane >> 3) & 1) * 8;
                int kc = k0 + (lane >> 4) * 4;
                unsigned addr = smem_u32(&As[buf][m][kc]);
                asm volatile("ldmatrix.sync.aligned.m8n8.x4.shared.b16 {%0,%1,%2,%3}, [%4];\n"
                    : "=r"(af[i][0]), "=r"(af[i][1]), "=r"(af[i][2]), "=r"(af[i][3]) : "r"(addr));
                #pragma unroll
                for (int r = 0; r < 4; r++)
                    asm volatile("cvt.rna.tf32.f32 %0, %0;\n" : "+r"(af[i][r]));
            }
            // B fragments via scalar LDS
            #pragma unroll
            for (int j = 0; j < 4; j++) {
                int n = wn*32 + j*8 + (lane >> 2);
                float b0f = Bs[buf][k0 + (lane & 3)][n];
                float b1f = Bs[buf][k0 + (lane & 3) + 4][n];
                asm volatile("cvt.rna.tf32.f32 %0, %1;\n" : "=r"(bf[j][0]) : "f"(b0f));
                asm volatile("cvt.rna.tf32.f32 %0, %1;\n" : "=r"(bf[j][1]) : "f"(b1f));
            }
            #pragma unroll
            for (int i = 0; i < 4; i++)
                #pragma unroll
                for (int j = 0; j < 4; j++) {
                    asm volatile(
                        "mma.sync.aligned.m16n8k8.row.col.f32.tf32.tf32.f32 "
                        "{%0,%1,%2,%3}, {%4,%5,%6,%7}, {%8,%9}, {%0,%1,%2,%3};\n"
                        : "+f"(acc[i][j][0]), "+f"(acc[i][j][1]), "+f"(acc[i][j][2]), "+f"(acc[i][j][3])
                        : "r"(af[i][0]), "r"(af[i][1]), "r"(af[i][2]), "r"(af[i][3]),
                          "r"(bf[j][0]), "r"(bf[j][1]));
                }
        }
        __syncthreads();
    }

    // epilogue: c-frag rows lane/4 (+8), cols 2*(lane%4) (+1)
    #pragma unroll
    for (int i = 0; i < 4; i++) {
        int r0 = wm*64 + i*16 + (lane >> 2);
        int r1 = r0 + 8;
        #pragma unroll
        for (int j = 0; j < 4; j++) {
            int c0 = wn*32 + j*8 + (lane & 3) * 2;
            float v0 = acc[i][j][0], v1 = acc[i][j][1];
            float v2 = acc[i][j][2], v3 = acc[i][j][3];
            if (Rg) {
                v0 += Rg[(size_t)r0*N + c0];   v1 += Rg[(size_t)r0*N + c0+1];
                v2 += Rg[(size_t)r1*N + c0];   v3 += Rg[(size_t)r1*N + c0+1];
            }
            Cg[(size_t)r0*N + c0]   = v0;  Cg[(size_t)r0*N + c0+1] = v1;
            Cg[(size_t)r1*N + c0]   = v2;  Cg[(size_t)r1*N + c0+1] = v3;
        }
    }
}

// ---------------- scores: S = Q Kᵀ / sqrt(DH) + bias, masked ----------------
__global__ __launch_bounds__(256) void scores_kernel(const int* __restrict__ mask)
{
    __shared__ float Qs[64][65];
    __shared__ float Ks[64][65];
    int b = blockIdx.z / HH, h = blockIdx.z % HH;
    int q0 = blockIdx.y * 64, k0 = blockIdx.x * 64;
    int tid = threadIdx.x;

    #pragma unroll
    for (int i = 0; i < 16; i++) {
        int idx = tid + i * 256;
        int r = idx >> 6, c = idx & 63;
        Qs[r][c] = g_q[(size_t)(b*TT + q0 + r) * DD + h*DHH + c];
        Ks[r][c] = g_k[(size_t)(b*TT + k0 + r) * DD + h*DHH + c];
    }
    __syncthreads();

    int ty = tid >> 4, tx = tid & 15;
    float acc[4][4];
    #pragma unroll
    for (int i = 0; i < 4; i++)
        #pragma unroll
        for (int j = 0; j < 4; j++) acc[i][j] = 0.f;

    #pragma unroll 8
    for (int kk = 0; kk < 64; kk++) {
        float rq[4], rk[4];
        #pragma unroll
        for (int i = 0; i < 4; i++) rq[i] = Qs[ty*4 + i][kk];
        #pragma unroll
        for (int j = 0; j < 4; j++) rk[j] = Ks[tx*4 + j][kk];
        #pragma unroll
        for (int i = 0; i < 4; i++)
            #pragma unroll
            for (int j = 0; j < 4; j++) acc[i][j] += rq[i] * rk[j];
    }

    #pragma unroll
    for (int i = 0; i < 4; i++) {
        int q = q0 + ty*4 + i;
        #pragma unroll
        for (int j = 0; j < 4; j++) {
            int k = k0 + tx*4 + j;
            float s = acc[i][j] * 0.125f + g_bias[(size_t)h*TT*TT + (size_t)q*TT + k];
            if (mask[(size_t)b*TT*TT + (size_t)q*TT + k] == 0) s = -1e9f;
            g_attn[(((size_t)(b*HH + h))*TT + q)*TT + k] = s;
        }
    }
}

// ---------------- softmax over last dim ----------------
__global__ void softmax_kernel()
{
    size_t row = blockIdx.x;
    float* p = g_attn + row * TT;
    __shared__ float red[256];
    float m = -1e30f;
    for (int i = threadIdx.x; i < TT; i += 256) m = fmaxf(m, p[i]);
    red[threadIdx.x] = m; __syncthreads();
    for (int o = 128; o > 0; o >>= 1) {
        if (threadIdx.x < o) red[threadIdx.x] = fmaxf(red[threadIdx.x], red[threadIdx.x + o]);
        __syncthreads();
    }
    m = red[0];
    __syncthreads();
    float s = 0.f;
    for (int i = threadIdx.x; i < TT; i += 256) {
        float e = __expf(p[i] - m);
        p[i] = e;
        s += e;
    }
    red[threadIdx.x] = s; __syncthreads();
    for (int o = 128; o > 0; o >>= 1) {
        if (threadIdx.x < o) red[threadIdx.x] += red[threadIdx.x + o];
        __syncthreads();
    }
    float inv = 1.0f / red[0];
    for (int i = threadIdx.x; i < TT; i += 256) p[i] *= inv;
}

// ---------------- ctx = P @ V ----------------
__global__ __launch_bounds__(256) void attnv_kernel()
{
    __shared__ float Ps[64][65];
    __shared__ float Vs[64][65];
    int b = blockIdx.y / HH, h = blockIdx.y % HH;
    int q0 = blockIdx.x * 64;
    int tid = threadIdx.x;
    int ty = tid >> 4, tx = tid & 15;

    float acc[4][4];
    #pragma unroll
    for (int i = 0; i < 4; i++)
        #pragma unroll
        for (int j = 0; j < 4; j++) acc[i][j] = 0.f;

    for (int kt = 0; kt < TT; kt += 64) {
        #pragma unroll
        for (int i = 0; i < 16; i++) {
            int idx = tid + i * 256;
            int r = idx >> 6, c = idx & 63;
            Ps[r][c] = g_attn[(((size_t)(b*HH + h))*TT + q0 + r)*TT + kt + c];
            Vs[r][c] = g_v[(size_t)(b*TT + kt + r) * DD + h*DHH + c];
        }
        __syncthreads();
        #pragma unroll 8
        for (int kk = 0; kk < 64; kk++) {
            float rp[4], rv[4];
            #pragma unroll
            for (int i = 0; i < 4; i++) rp[i] = Ps[ty*4 + i][kk];
            #pragma unroll
            for (int j = 0; j < 4; j++) rv[j] = Vs[kk][tx*4 + j];
            #pragma unroll
            for (int i = 0; i < 4; i++)
                #pragma unroll
                for (int j = 0; j < 4; j++) acc[i][j] += rp[i] * rv[j];
        }
        __syncthreads();
    }
    #pragma unroll
    for (int i = 0; i < 4; i++)
        #pragma unroll
        for (int j = 0; j < 4; j++)
            g_ctx[(size_t)(b*TT + q0 + ty*4 + i) * DD + h*DHH + tx*4 + j] = acc[i][j];
}

// ---------------- GEGLU ----------------
__global__ void geglu_kernel()
{
    size_t idx = (size_t)blockIdx.x * blockDim.x + threadIdx.x;
    if (idx >= (size_t)BT * 2 * DD) return;
    size_t r = idx / (2*DD);
    int c = (int)(idx % (2*DD));
    float p1 = g_ffn1[r * 4*DD + c];
    float p2 = g_ffn1[r * 4*DD + 2*DD + c];
    float gelu = 0.5f * p2 * (1.0f + erff(p2 * 0.70710678118654752f));
    g_gg[idx] = p1 * gelu;
}

// ---------------- host launcher ----------------
extern "C" void kernel_launch(void* const* d_in, const int* in_sizes, int n_in,
                              void* d_out, int out_size)
{
    const float* x       = (const float*)d_in[0];
    const int*   mask    = (const int*)  d_in[1];
    const float* cond    = (const float*)d_in[2];
    const float* norm1_w = (const float*)d_in[3];
    const float* f1gw    = (const float*)d_in[4];
    const float* f1gb    = (const float*)d_in[5];
    const float* f1bw    = (const float*)d_in[6];
    const float* f1bb    = (const float*)d_in[7];
    const float* wq      = (const float*)d_in[8];
    const float* wk      = (const float*)d_in[9];
    const float* wv      = (const float*)d_in[10];
    const float* wo      = (const float*)d_in[11];
    const float* rel_emb = (const float*)d_in[12];
    const float* norm3_w = (const float*)d_in[13];
    const float* f3gw    = (const float*)d_in[14];
    const float* f3gb    = (const float*)d_in[15];
    const float* f3bw    = (const float*)d_in[16];
    const float* f3bb    = (const float*)d_in[17];
    const float* w1      = (const float*)d_in[18];
    const float* w2      = (const float*)d_in[19];
    float* out = (float*)d_out;
    float* outbias = (out_size >= BTD + BIAS_ELEMS) ? out + BTD : nullptr;

    float *p_g1, *p_b1, *p_g3, *p_b3, *p_y, *p_q, *p_k, *p_v, *p_ctx, *p_x1, *p_ffn1, *p_gg;
    cudaGetSymbolAddress((void**)&p_g1, g_gamma1);
    cudaGetSymbolAddress((void**)&p_b1, g_beta1);
    cudaGetSymbolAddress((void**)&p_g3, g_gamma3);
    cudaGetSymbolAddress((void**)&p_b3, g_beta3);
    cudaGetSymbolAddress((void**)&p_y,  g_y);
    cudaGetSymbolAddress((void**)&p_q,  g_q);
    cudaGetSymbolAddress((void**)&p_k,  g_k);
    cudaGetSymbolAddress((void**)&p_v,  g_v);
    cudaGetSymbolAddress((void**)&p_ctx, g_ctx);
    cudaGetSymbolAddress((void**)&p_x1, g_x1);
    cudaGetSymbolAddress((void**)&p_ffn1, g_ffn1);
    cudaGetSymbolAddress((void**)&p_gg, g_gg);

    // 1) FiLM parameters + position bias
    film_params_kernel<<<(BB*DD + 255)/256, 256>>>(cond, f1gw, f1gb, f1bw, f1bb,
                                                   f3gw, f3gb, f3bw, f3bb);
    bias_kernel<<<(TT*TT + 255)/256, 256>>>(rel_emb, outbias);

    // 2) y = film(rmsnorm(x))
    rmsnorm_film_kernel<<<BT, 256>>>(x, norm1_w, p_g1, p_b1, p_y);

    // 3) Q/K/V projections (tf32 tensor cores)
    dim3 gproj(DD/GBN, BT/GBM);
    gemm_tf32_kernel<<<gproj, 256>>>(BT, DD, DD, p_y, wq, nullptr, p_q);
    gemm_tf32_kernel<<<gproj, 256>>>(BT, DD, DD, p_y, wk, nullptr, p_k);
    gemm_tf32_kernel<<<gproj, 256>>>(BT, DD, DD, p_y, wv, nullptr, p_v);

    // 4) attention
    scores_kernel<<<dim3(TT/64, TT/64, BB*HH), 256>>>(mask);
    softmax_kernel<<<BB*HH*TT, 256>>>();
    attnv_kernel<<<dim3(TT/64, BB*HH), 256>>>();

    // 5) output projection + residual -> x1
    gemm_tf32_kernel<<<gproj, 256>>>(BT, DD, DD, p_ctx, wo, x, p_x1);

    // 6) y2 = film3(rmsnorm(x1))
    rmsnorm_film_kernel<<<BT, 256>>>(p_x1, norm3_w, p_g3, p_b3, p_y);

    // 7) FFN
    gemm_tf32_kernel<<<dim3(4*DD/GBN, BT/GBM), 256>>>(BT, 4*DD, DD, p_y, w1, nullptr, p_ffn1);
    geglu_kernel<<<(int)(((size_t)BT*2*DD + 255)/256), 256>>>();
    gemm_tf32_kernel<<<dim3(DD/GBN, BT/GBM), 256>>>(BT, DD, 2*DD, p_gg, w2, p_x1, out);
}

// round 7
// speedup vs baseline: 2.8194x; 1.5222x over previous
#include <cuda_runtime.h>
#include <math.h>

#define BB 4
#define TT 1024
#define DD 1024
#define HH 16
#define DHH 64
#define DCC 64
#define BT (BB*TT)        // 4096
#define BTD (BB*TT*DD)    // 4194304
#define BIAS_ELEMS (HH*TT*TT) // 16777216

// ---------------- scratch (device globals; no allocation) ----------------
__device__ float g_gamma1[BB*DD];
__device__ float g_beta1 [BB*DD];
__device__ float g_gamma3[BB*DD];
__device__ float g_beta3 [BB*DD];
__device__ float g_y   [BTD];
__device__ float g_q   [BTD];
__device__ float g_k   [BTD];
__device__ float g_v   [BTD];
__device__ float g_ctx [BTD];
__device__ float g_x1  [BTD];
__device__ float g_biasrel[HH*2048];          // per-head bias by relative position
__device__ float g_ffn1[(size_t)BT*4*DD];
__device__ float g_gg  [(size_t)BT*2*DD];

__device__ __forceinline__ unsigned smem_u32(const void* p) {
    return (unsigned)__cvta_generic_to_shared(p);
}
__device__ __forceinline__ unsigned f2tf(float f) {
    unsigned u;
    asm("cvt.rna.tf32.f32 %0, %1;\n" : "=r"(u) : "f"(f));
    return u;
}

// ---------------- FiLM params ----------------
__global__ void film_params_kernel(const float* __restrict__ cond,
    const float* __restrict__ g1w, const float* __restrict__ g1b,
    const float* __restrict__ b1w, const float* __restrict__ b1b,
    const float* __restrict__ g3w, const float* __restrict__ g3b,
    const float* __restrict__ b3w, const float* __restrict__ b3b)
{
    int idx = blockIdx.x * blockDim.x + threadIdx.x;
    if (idx >= BB*DD) return;
    int b = idx / DD, d = idx % DD;
    float s1 = 0.f, s2 = 0.f, s3 = 0.f, s4 = 0.f;
    #pragma unroll 8
    for (int c = 0; c < DCC; c++) {
        float cv = cond[b*DCC + c];
        s1 += cv * g1w[c*DD + d];
        s2 += cv * b1w[c*DD + d];
        s3 += cv * g3w[c*DD + d];
        s4 += cv * b3w[c*DD + d];
    }
    g_gamma1[idx] = s1 + g1b[d];
    g_beta1 [idx] = s2 + b1b[d];
    g_gamma3[idx] = s3 + g3b[d];
    g_beta3 [idx] = s4 + b3b[d];
}

// ---------------- T5 bucket helper ----------------
__device__ __forceinline__ int t5_bucket(int rp) {
    int bucket = (rp > 0) ? 16 : 0;
    int arp = rp < 0 ? -rp : rp;
    int off;
    if (arp < 8) {
        off = arp;
    } else {
        float l = logf((float)arp * 0.125f) / logf(16.0f) * 8.0f;
        off = 8 + (int)l;
        if (off > 15) off = 15;
    }
    return bucket + off;
}

// per-head bias LUT over relative position: g_biasrel[h*2048 + rel+1023]
__global__ void biasrel_kernel(const float* __restrict__ rel_emb)
{
    int idx = blockIdx.x * blockDim.x + threadIdx.x;
    if (idx >= 2047) return;
    int bucket = t5_bucket(idx - 1023);
    #pragma unroll
    for (int h = 0; h < HH; h++)
        g_biasrel[h*2048 + idx] = rel_emb[bucket*HH + h];
}

// bias output tensor [1,H,T,T]
__global__ void bias_out_kernel(const float* __restrict__ rel_emb, float* __restrict__ outbias)
{
    int idx = blockIdx.x * blockDim.x + threadIdx.x;
    if (idx >= TT*TT) return;
    int q = idx / TT, k = idx % TT;
    int bucket = t5_bucket(k - q);
    #pragma unroll
    for (int h = 0; h < HH; h++)
        outbias[(size_t)h*TT*TT + idx] = rel_emb[bucket*HH + h];
}

// ---------------- RMSNorm + FiLM ----------------
__global__ void rmsnorm_film_kernel(const float* __restrict__ x, const float* __restrict__ w,
                                    const float* __restrict__ gamma, const float* __restrict__ beta,
                                    float* __restrict__ y)
{
    int row = blockIdx.x;
    int b = row / TT;
    const float* xr = x + (size_t)row * DD;
    float* yr = y + (size_t)row * DD;
    __shared__ float red[256];
    float s = 0.f;
    for (int d = threadIdx.x; d < DD; d += 256) { float v = xr[d]; s += v*v; }
    red[threadIdx.x] = s; __syncthreads();
    for (int o = 128; o > 0; o >>= 1) {
        if (threadIdx.x < o) red[threadIdx.x] += red[threadIdx.x + o];
        __syncthreads();
    }
    float rs = rsqrtf(red[0] * (1.0f/DD) + 1e-6f);
    for (int d = threadIdx.x; d < DD; d += 256) {
        float v = w[d] * xr[d] * rs;
        yr[d] = v * (gamma[b*DD + d] + 1.0f) + beta[b*DD + d];
    }
}

// ---------------- TF32 tensor-core GEMM 128x128x16 ----------------
#define GBM 128
#define GBN 128
#define GBK 16

__global__ __launch_bounds__(256) void gemm_tf32_kernel(int M, int N, int K,
    const float* __restrict__ A, const float* __restrict__ B,
    const float* __restrict__ Res, float* __restrict__ C)
{
    __shared__ float As[2][GBM][GBK+4];
    __shared__ float Bs[2][GBK][GBN+8];

    int tid = threadIdx.x;
    int wid = tid >> 5, lane = tid & 31;
    int wm = wid >> 2, wn = wid & 3;

    const float* Ag = A + (size_t)blockIdx.y * GBM * K;
    const float* Bg = B + blockIdx.x * GBN;
    float* Cg = C + (size_t)blockIdx.y * GBM * N + blockIdx.x * GBN;
    const float* Rg = Res ? Res + (size_t)blockIdx.y * GBM * N + blockIdx.x * GBN : nullptr;

    float acc[4][4][4];
    #pragma unroll
    for (int i = 0; i < 4; i++)
        #pragma unroll
        for (int j = 0; j < 4; j++)
            #pragma unroll
            for (int r = 0; r < 4; r++) acc[i][j][r] = 0.f;

    int a_r0 = tid >> 2,       a_c = (tid & 3) * 4;
    int b_r0 = tid >> 5,       b_c = (tid & 31) * 4;

    int nk = K / GBK;
    {
        unsigned d0 = smem_u32(&As[0][a_r0][a_c]);
        unsigned d1 = smem_u32(&As[0][a_r0+64][a_c]);
        asm volatile("cp.async.cg.shared.global [%0], [%1], 16;\n" :: "r"(d0), "l"(Ag + (size_t)a_r0*K + a_c));
        asm volatile("cp.async.cg.shared.global [%0], [%1], 16;\n" :: "r"(d1), "l"(Ag + (size_t)(a_r0+64)*K + a_c));
        unsigned e0 = smem_u32(&Bs[0][b_r0][b_c]);
        unsigned e1 = smem_u32(&Bs[0][b_r0+8][b_c]);
        asm volatile("cp.async.cg.shared.global [%0], [%1], 16;\n" :: "r"(e0), "l"(Bg + (size_t)b_r0*N + b_c));
        asm volatile("cp.async.cg.shared.global [%0], [%1], 16;\n" :: "r"(e1), "l"(Bg + (size_t)(b_r0+8)*N + b_c));
        asm volatile("cp.async.commit_group;\n");
    }

    for (int t = 0; t < nk; t++) {
        if (t + 1 < nk) {
            int nb = (t+1) & 1;
            int kt = (t+1) * GBK;
            unsigned d0 = smem_u32(&As[nb][a_r0][a_c]);
            unsigned d1 = smem_u32(&As[nb][a_r0+64][a_c]);
            asm volatile("cp.async.cg.shared.global [%0], [%1], 16;\n" :: "r"(d0), "l"(Ag + (size_t)a_r0*K + kt + a_c));
            asm volatile("cp.async.cg.shared.global [%0], [%1], 16;\n" :: "r"(d1), "l"(Ag + (size_t)(a_r0+64)*K + kt + a_c));
            unsigned e0 = smem_u32(&Bs[nb][b_r0][b_c]);
            unsigned e1 = smem_u32(&Bs[nb][b_r0+8][b_c]);
            asm volatile("cp.async.cg.shared.global [%0], [%1], 16;\n" :: "r"(e0), "l"(Bg + (size_t)(kt+b_r0)*N + b_c));
            asm volatile("cp.async.cg.shared.global [%0], [%1], 16;\n" :: "r"(e1), "l"(Bg + (size_t)(kt+b_r0+8)*N + b_c));
        }
        asm volatile("cp.async.commit_group;\n");
        asm volatile("cp.async.wait_group 1;\n");
        __syncthreads();

        int buf = t & 1;
        #pragma unroll
        for (int kk = 0; kk < 2; kk++) {
            int k0 = kk * 8;
            unsigned af[4][4];
            unsigned bf[4][2];
            #pragma unroll
            for (int i = 0; i < 4; i++) {
                int m = wm*64 + i*16 + (lane & 7) + ((lane >> 3) & 1) * 8;
                int kc = k0 + (lane >> 4) * 4;
                unsigned addr = smem_u32(&As[buf][m][kc]);
                asm volatile("ldmatrix.sync.aligned.m8n8.x4.shared.b16 {%0,%1,%2,%3}, [%4];\n"
                    : "=r"(af[i][0]), "=r"(af[i][1]), "=r"(af[i][2]), "=r"(af[i][3]) : "r"(addr));
                #pragma unroll
                for (int r = 0; r < 4; r++)
                    asm volatile("cvt.rna.tf32.f32 %0, %0;\n" : "+r"(af[i][r]));
            }
            #pragma unroll
            for (int j = 0; j < 4; j++) {
                int n = wn*32 + j*8 + (lane >> 2);
                bf[j][0] = f2tf(Bs[buf][k0 + (lane & 3)][n]);
                bf[j][1] = f2tf(Bs[buf][k0 + (lane & 3) + 4][n]);
            }
            #pragma unroll
            for (int i = 0; i < 4; i++)
                #pragma unroll
                for (int j = 0; j < 4; j++) {
                    asm volatile(
                        "mma.sync.aligned.m16n8k8.row.col.f32.tf32.tf32.f32 "
                        "{%0,%1,%2,%3}, {%4,%5,%6,%7}, {%8,%9}, {%0,%1,%2,%3};\n"
                        : "+f"(acc[i][j][0]), "+f"(acc[i][j][1]), "+f"(acc[i][j][2]), "+f"(acc[i][j][3])
                        : "r"(af[i][0]), "r"(af[i][1]), "r"(af[i][2]), "r"(af[i][3]),
                          "r"(bf[j][0]), "r"(bf[j][1]));
                }
        }
        __syncthreads();
    }

    #pragma unroll
    for (int i = 0; i < 4; i++) {
        int r0 = wm*64 + i*16 + (lane >> 2);
        int r1 = r0 + 8;
        #pragma unroll
        for (int j = 0; j < 4; j++) {
            int c0 = wn*32 + j*8 + (lane & 3) * 2;
            float v0 = acc[i][j][0], v1 = acc[i][j][1];
            float v2 = acc[i][j][2], v3 = acc[i][j][3];
            if (Rg) {
                v0 += Rg[(size_t)r0*N + c0];   v1 += Rg[(size_t)r0*N + c0+1];
                v2 += Rg[(size_t)r1*N + c0];   v3 += Rg[(size_t)r1*N + c0+1];
            }
            Cg[(size_t)r0*N + c0]   = v0;  Cg[(size_t)r0*N + c0+1] = v1;
            Cg[(size_t)r1*N + c0]   = v2;  Cg[(size_t)r1*N + c0+1] = v3;
        }
    }
}

// ---------------- fused flash attention (tf32 MMA) ----------------
// grid: (T/64, B*H); block: 128 threads (4 warps, each owns 16 q-rows)
// smem via dynamic allocation (69.5 KB > 48 KB static cap)
struct FlashSmem {
    float Qs[64][68];
    float Ks[64][68];
    float Vs[64][68];
    float Ps[4][16][72];
    float Sb[128];          // bias window: 127 entries used
};

__global__ __launch_bounds__(128) void flash_attn_kernel(const int* __restrict__ mask)
{
    extern __shared__ char fa_smem_raw[];
    FlashSmem& S = *reinterpret_cast<FlashSmem*>(fa_smem_raw);

    int qt = blockIdx.x, bh = blockIdx.y;
    int b = bh / HH, h = bh % HH;
    int q0 = qt * 64;
    int tid = threadIdx.x, wid = tid >> 5, lane = tid & 31;
    int lq = lane >> 2, lk = lane & 3;   // quad row / quad col

    // fill Q tile, prescaled by 1/sqrt(DH)=0.125
    for (int i = tid; i < 64*16; i += 128) {
        int r = i >> 4, c4 = (i & 15) * 4;
        float4 v = *reinterpret_cast<const float4*>(&g_q[(size_t)(b*TT + q0 + r)*DD + h*DHH + c4]);
        S.Qs[r][c4+0] = v.x * 0.125f; S.Qs[r][c4+1] = v.y * 0.125f;
        S.Qs[r][c4+2] = v.z * 0.125f; S.Qs[r][c4+3] = v.w * 0.125f;
    }

    float o[8][4];
    #pragma unroll
    for (int n = 0; n < 8; n++)
        #pragma unroll
        for (int r = 0; r < 4; r++) o[n][r] = 0.f;
    float mrow[2] = { -3.0e38f, -3.0e38f };
    float lrow[2] = { 0.f, 0.f };

    int qrel = wid*16 + lq;            // q row within 64-tile (row-half e adds 8)

    for (int kt0 = 0; kt0 < TT; kt0 += 64) {
        __syncthreads();
        // fill K, V tiles
        for (int i = tid; i < 64*16; i += 128) {
            int r = i >> 4, c4 = (i & 15) * 4;
            float4 kv = *reinterpret_cast<const float4*>(&g_k[(size_t)(b*TT + kt0 + r)*DD + h*DHH + c4]);
            S.Ks[r][c4+0] = kv.x; S.Ks[r][c4+1] = kv.y; S.Ks[r][c4+2] = kv.z; S.Ks[r][c4+3] = kv.w;
            float4 vv = *reinterpret_cast<const float4*>(&g_v[(size_t)(b*TT + kt0 + r)*DD + h*DHH + c4]);
            S.Vs[r][c4+0] = vv.x; S.Vs[r][c4+1] = vv.y; S.Vs[r][c4+2] = vv.z; S.Vs[r][c4+3] = vv.w;
        }
        // bias window: rel = kt0-q0 + (kr-qr), kr-qr in [-63,63] -> Sb[kr-qr+63]
        if (tid < 127) S.Sb[tid] = g_biasrel[h*2048 + (kt0 - q0 + 960) + tid];
        __syncthreads();

        // ---- S = Q @ K^T ----
        float sacc[8][4];
        #pragma unroll
        for (int n = 0; n < 8; n++)
            #pragma unroll
            for (int r = 0; r < 4; r++) sacc[n][r] = 0.f;

        #pragma unroll
        for (int ks = 0; ks < 8; ks++) {
            int kc = ks*8 + lk;
            unsigned aq[4];
            aq[0] = f2tf(S.Qs[qrel  ][kc  ]);
            aq[1] = f2tf(S.Qs[qrel+8][kc  ]);
            aq[2] = f2tf(S.Qs[qrel  ][kc+4]);
            aq[3] = f2tf(S.Qs[qrel+8][kc+4]);
            #pragma unroll
            for (int n = 0; n < 8; n++) {
                unsigned bk0 = f2tf(S.Ks[n*8 + lq][kc  ]);
                unsigned bk1 = f2tf(S.Ks[n*8 + lq][kc+4]);
                asm volatile(
                    "mma.sync.aligned.m16n8k8.row.col.f32.tf32.tf32.f32 "
                    "{%0,%1,%2,%3}, {%4,%5,%6,%7}, {%8,%9}, {%0,%1,%2,%3};\n"
                    : "+f"(sacc[n][0]), "+f"(sacc[n][1]), "+f"(sacc[n][2]), "+f"(sacc[n][3])
                    : "r"(aq[0]), "r"(aq[1]), "r"(aq[2]), "r"(aq[3]), "r"(bk0), "r"(bk1));
            }
        }

        // ---- bias + mask + online softmax ----
        float mnew[2] = { mrow[0], mrow[1] };
        #pragma unroll
        for (int n = 0; n < 8; n++) {
            #pragma unroll
            for (int e = 0; e < 2; e++) {
                int qr = qrel + e*8;
                const int* mrowp = mask + ((size_t)(b*TT + q0 + qr))*TT + kt0;
                #pragma unroll
                for (int c = 0; c < 2; c++) {
                    int kr = n*8 + 2*lk + c;
                    float s = sacc[n][e*2+c] + S.Sb[kr - qr + 63];
                    if (mrowp[kr] == 0) s = -1e9f;
                    sacc[n][e*2+c] = s;
                    mnew[e] = fmaxf(mnew[e], s);
                }
            }
        }
        #pragma unroll
        for (int e = 0; e < 2; e++) {
            mnew[e] = fmaxf(mnew[e], __shfl_xor_sync(0xffffffffu, mnew[e], 1));
            mnew[e] = fmaxf(mnew[e], __shfl_xor_sync(0xffffffffu, mnew[e], 2));
        }
        float alpha[2], rs[2] = {0.f, 0.f};
        alpha[0] = __expf(mrow[0] - mnew[0]);
        alpha[1] = __expf(mrow[1] - mnew[1]);
        mrow[0] = mnew[0]; mrow[1] = mnew[1];

        #pragma unroll
        for (int n = 0; n < 8; n++) {
            #pragma unroll
            for (int e = 0; e < 2; e++) {
                float p0 = __expf(sacc[n][e*2+0] - mnew[e]);
                float p1 = __expf(sacc[n][e*2+1] - mnew[e]);
                rs[e] += p0 + p1;
                // store P (tf32-rounded) into warp-private smem
                float2 pv;
                pv.x = __uint_as_float(f2tf(p0));
                pv.y = __uint_as_float(f2tf(p1));
                *reinterpret_cast<float2*>(&S.Ps[wid][lq + e*8][n*8 + 2*lk]) = pv;
            }
        }
        #pragma unroll
        for (int e = 0; e < 2; e++) {
            rs[e] += __shfl_xor_sync(0xffffffffu, rs[e], 1);
            rs[e] += __shfl_xor_sync(0xffffffffu, rs[e], 2);
            lrow[e] = lrow[e] * alpha[e] + rs[e];
        }
        // rescale O accumulators
        #pragma unroll
        for (int n = 0; n < 8; n++) {
            o[n][0] *= alpha[0]; o[n][1] *= alpha[0];
            o[n][2] *= alpha[1]; o[n][3] *= alpha[1];
        }
        __syncwarp();

        // ---- O += P @ V ----
        #pragma unroll
        for (int ks = 0; ks < 8; ks++) {
            int kc = ks*8 + lk;
            unsigned ap[4];
            ap[0] = __float_as_uint(S.Ps[wid][lq  ][kc  ]);
            ap[1] = __float_as_uint(S.Ps[wid][lq+8][kc  ]);
            ap[2] = __float_as_uint(S.Ps[wid][lq  ][kc+4]);
            ap[3] = __float_as_uint(S.Ps[wid][lq+8][kc+4]);
            #pragma unroll
            for (int n = 0; n < 8; n++) {
                unsigned bv0 = f2tf(S.Vs[kc  ][n*8 + lq]);
                unsigned bv1 = f2tf(S.Vs[kc+4][n*8 + lq]);
                asm volatile(
                    "mma.sync.aligned.m16n8k8.row.col.f32.tf32.tf32.f32 "
                    "{%0,%1,%2,%3}, {%4,%5,%6,%7}, {%8,%9}, {%0,%1,%2,%3};\n"
                    : "+f"(o[n][0]), "+f"(o[n][1]), "+f"(o[n][2]), "+f"(o[n][3])
                    : "r"(ap[0]), "r"(ap[1]), "r"(ap[2]), "r"(ap[3]), "r"(bv0), "r"(bv1));
            }
        }
        __syncwarp();
    }

    // ---- epilogue: O /= l, write ctx ----
    float inv0 = 1.0f / lrow[0], inv1 = 1.0f / lrow[1];
    #pragma unroll
    for (int e = 0; e < 2; e++) {
        int qg = b*TT + q0 + qrel + e*8;
        float inv = e ? inv1 : inv0;
        #pragma unroll
        for (int n = 0; n < 8; n++) {
            float2 w;
            w.x = o[n][e*2+0] * inv;
            w.y = o[n][e*2+1] * inv;
            *reinterpret_cast<float2*>(&g_ctx[(size_t)qg*DD + h*DHH + n*8 + 2*lk]) = w;
        }
    }
}

// ---------------- GEGLU ----------------
__global__ void geglu_kernel()
{
    size_t idx = (size_t)blockIdx.x * blockDim.x + threadIdx.x;
    if (idx >= (size_t)BT * 2 * DD) return;
    size_t r = idx / (2*DD);
    int c = (int)(idx % (2*DD));
    float p1 = g_ffn1[r * 4*DD + c];
    float p2 = g_ffn1[r * 4*DD + 2*DD + c];
    float gelu = 0.5f * p2 * (1.0f + erff(p2 * 0.70710678118654752f));
    g_gg[idx] = p1 * gelu;
}

// ---------------- host launcher ----------------
extern "C" void kernel_launch(void* const* d_in, const int* in_sizes, int n_in,
                              void* d_out, int out_size)
{
    const float* x       = (const float*)d_in[0];
    const int*   mask    = (const int*)  d_in[1];
    const float* cond    = (const float*)d_in[2];
    const float* norm1_w = (const float*)d_in[3];
    const float* f1gw    = (const float*)d_in[4];
    const float* f1gb    = (const float*)d_in[5];
    const float* f1bw    = (const float*)d_in[6];
    const float* f1bb    = (const float*)d_in[7];
    const float* wq      = (const float*)d_in[8];
    const float* wk      = (const float*)d_in[9];
    const float* wv      = (const float*)d_in[10];
    const float* wo      = (const float*)d_in[11];
    const float* rel_emb = (const float*)d_in[12];
    const float* norm3_w = (const float*)d_in[13];
    const float* f3gw    = (const float*)d_in[14];
    const float* f3gb    = (const float*)d_in[15];
    const float* f3bw    = (const float*)d_in[16];
    const float* f3bb    = (const float*)d_in[17];
    const float* w1      = (const float*)d_in[18];
    const float* w2      = (const float*)d_in[19];
    float* out = (float*)d_out;
    float* outbias = (out_size >= BTD + BIAS_ELEMS) ? out + BTD : nullptr;

    float *p_g1, *p_b1, *p_g3, *p_b3, *p_y, *p_q, *p_k, *p_v, *p_ctx, *p_x1, *p_ffn1, *p_gg;
    cudaGetSymbolAddress((void**)&p_g1, g_gamma1);
    cudaGetSymbolAddress((void**)&p_b1, g_beta1);
    cudaGetSymbolAddress((void**)&p_g3, g_gamma3);
    cudaGetSymbolAddress((void**)&p_b3, g_beta3);
    cudaGetSymbolAddress((void**)&p_y,  g_y);
    cudaGetSymbolAddress((void**)&p_q,  g_q);
    cudaGetSymbolAddress((void**)&p_k,  g_k);
    cudaGetSymbolAddress((void**)&p_v,  g_v);
    cudaGetSymbolAddress((void**)&p_ctx, g_ctx);
    cudaGetSymbolAddress((void**)&p_x1, g_x1);
    cudaGetSymbolAddress((void**)&p_ffn1, g_ffn1);
    cudaGetSymbolAddress((void**)&p_gg, g_gg);

    // opt-in to >48KB dynamic smem for flash kernel (idempotent, capture-safe)
    cudaFuncSetAttribute(flash_attn_kernel,
                         cudaFuncAttributeMaxDynamicSharedMemorySize,
                         (int)sizeof(FlashSmem));

    // 1) FiLM params + bias LUT + bias output
    film_params_kernel<<<(BB*DD + 255)/256, 256>>>(cond, f1gw, f1gb, f1bw, f1bb,
                                                   f3gw, f3gb, f3bw, f3bb);
    biasrel_kernel<<<(2047 + 255)/256, 256>>>(rel_emb);
    if (outbias)
        bias_out_kernel<<<(TT*TT + 255)/256, 256>>>(rel_emb, outbias);

    // 2) y = film(rmsnorm(x))
    rmsnorm_film_kernel<<<BT, 256>>>(x, norm1_w, p_g1, p_b1, p_y);

    // 3) Q/K/V projections (tf32 tensor cores)
    dim3 gproj(DD/GBN, BT/GBM);
    gemm_tf32_kernel<<<gproj, 256>>>(BT, DD, DD, p_y, wq, nullptr, p_q);
    gemm_tf32_kernel<<<gproj, 256>>>(BT, DD, DD, p_y, wk, nullptr, p_k);
    gemm_tf32_kernel<<<gproj, 256>>>(BT, DD, DD, p_y, wv, nullptr, p_v);

    // 4) fused flash attention -> g_ctx
    flash_attn_kernel<<<dim3(TT/64, BB*HH), 128, sizeof(FlashSmem)>>>(mask);

    // 5) output projection + residual -> x1
    gemm_tf32_kernel<<<gproj, 256>>>(BT, DD, DD, p_ctx, wo, x, p_x1);

    // 6) y2 = film3(rmsnorm(x1))
    rmsnorm_film_kernel<<<BT, 256>>>(p_x1, norm3_w, p_g3, p_b3, p_y);

    // 7) FFN
    gemm_tf32_kernel<<<dim3(4*DD/GBN, BT/GBM), 256>>>(BT, 4*DD, DD, p_y, w1, nullptr, p_ffn1);
    geglu_kernel<<<(int)(((size_t)BT*2*DD + 255)/256), 256>>>();
    gemm_tf32_kernel<<<dim3(DD/GBN, BT/GBM), 256>>>(BT, DD, 2*DD, p_gg, w2, p_x1, out);
}

// round 9
// speedup vs baseline: 2.8375x; 1.0064x over previous
#include <cuda_runtime.h>
#include <math.h>

#define BB 4
#define TT 1024
#define DD 1024
#define HH 16
#define DHH 64
#define DCC 64
#define BT (BB*TT)        // 4096
#define BTD (BB*TT*DD)    // 4194304
#define BIAS_ELEMS (HH*TT*TT) // 16777216

// ---------------- scratch (device globals; no allocation) ----------------
__device__ float g_gamma1[BB*DD];
__device__ float g_beta1 [BB*DD];
__device__ float g_gamma3[BB*DD];
__device__ float g_beta3 [BB*DD];
__device__ float g_y   [BTD];
__device__ float g_q   [BTD];
__device__ float g_k   [BTD];
__device__ float g_v   [BTD];
__device__ float g_ctx [BTD];
__device__ float g_x1  [BTD];
__device__ float g_biasrel[HH*2048];
__device__ float g_ffn1[(size_t)BT*4*DD];
__device__ float g_gg  [(size_t)BT*2*DD];
// transposed (K-major) tf32-rounded weights
__device__ float g_wqT[DD*DD];
__device__ float g_wkT[DD*DD];
__device__ float g_wvT[DD*DD];
__device__ float g_woT[DD*DD];
__device__ float g_w1T[(size_t)4*DD*DD];
__device__ float g_w2T[(size_t)2*DD*DD];

__device__ __forceinline__ unsigned smem_u32(const void* p) {
    return (unsigned)__cvta_generic_to_shared(p);
}
__device__ __forceinline__ unsigned f2tf(float f) {
    unsigned u;
    asm("cvt.rna.tf32.f32 %0, %1;\n" : "=r"(u) : "f"(f));
    return u;
}
__device__ __forceinline__ float f2tf_f(float f) { return __uint_as_float(f2tf(f)); }

// ---------------- FiLM params ----------------
__global__ void film_params_kernel(const float* __restrict__ cond,
    const float* __restrict__ g1w, const float* __restrict__ g1b,
    const float* __restrict__ b1w, const float* __restrict__ b1b,
    const float* __restrict__ g3w, const float* __restrict__ g3b,
    const float* __restrict__ b3w, const float* __restrict__ b3b)
{
    int idx = blockIdx.x * blockDim.x + threadIdx.x;
    if (idx >= BB*DD) return;
    int b = idx / DD, d = idx % DD;
    float s1 = 0.f, s2 = 0.f, s3 = 0.f, s4 = 0.f;
    #pragma unroll 8
    for (int c = 0; c < DCC; c++) {
        float cv = cond[b*DCC + c];
        s1 += cv * g1w[c*DD + d];
        s2 += cv * b1w[c*DD + d];
        s3 += cv * g3w[c*DD + d];
        s4 += cv * b3w[c*DD + d];
    }
    g_gamma1[idx] = s1 + g1b[d];
    g_beta1 [idx] = s2 + b1b[d];
    g_gamma3[idx] = s3 + g3b[d];
    g_beta3 [idx] = s4 + b3b[d];
}

// ---------------- T5 bucket ----------------
__device__ __forceinline__ int t5_bucket(int rp) {
    int bucket = (rp > 0) ? 16 : 0;
    int arp = rp < 0 ? -rp : rp;
    int off;
    if (arp < 8) {
        off = arp;
    } else {
        float l = logf((float)arp * 0.125f) / logf(16.0f) * 8.0f;
        off = 8 + (int)l;
        if (off > 15) off = 15;
    }
    return bucket + off;
}

__global__ void biasrel_kernel(const float* __restrict__ rel_emb)
{
    int idx = blockIdx.x * blockDim.x + threadIdx.x;
    if (idx >= 2047) return;
    int bucket = t5_bucket(idx - 1023);
    #pragma unroll
    for (int h = 0; h < HH; h++)
        g_biasrel[h*2048 + idx] = rel_emb[bucket*HH + h];
}

__global__ void bias_out_kernel(const float* __restrict__ rel_emb, float* __restrict__ outbias)
{
    int idx = blockIdx.x * blockDim.x + threadIdx.x;
    if (idx >= TT*TT) return;
    int q = idx / TT, k = idx % TT;
    int bucket = t5_bucket(k - q);
    #pragma unroll
    for (int h = 0; h < HH; h++)
        outbias[(size_t)h*TT*TT + idx] = rel_emb[bucket*HH + h];
}

// ---------------- weight transpose + tf32 round: src[K][N] -> dst[N][K] ----------------
__global__ void transpose_tf32_kernel(const float* __restrict__ src, float* __restrict__ dst,
                                      int Kd, int Nd)
{
    __shared__ float ts[32][33];
    int n0 = blockIdx.x*32, k0 = blockIdx.y*32;
    int tx = threadIdx.x, ty = threadIdx.y;   // 32 x 8
    #pragma unroll
    for (int i = 0; i < 32; i += 8)
        ts[ty+i][tx] = src[(size_t)(k0+ty+i)*Nd + n0+tx];
    __syncthreads();
    #pragma unroll
    for (int i = 0; i < 32; i += 8)
        dst[(size_t)(n0+ty+i)*Kd + k0+tx] = f2tf_f(ts[tx][ty+i]);
}

// ---------------- RMSNorm + FiLM (float4, tf32-rounded output) ----------------
__global__ void rmsnorm_film_kernel(const float* __restrict__ x, const float* __restrict__ w,
                                    const float* __restrict__ gamma, const float* __restrict__ beta,
                                    float* __restrict__ y)
{
    int row = blockIdx.x;
    int b = row / TT;
    const float* xr = x + (size_t)row * DD;
    float* yr = y + (size_t)row * DD;
    int d4 = threadIdx.x * 4;   // 256 threads x 4 floats = 1024 = DD
    float4 v = *reinterpret_cast<const float4*>(&xr[d4]);
    float s = v.x*v.x + v.y*v.y + v.z*v.z + v.w*v.w;
    __shared__ float red[256];
    red[threadIdx.x] = s; __syncthreads();
    for (int o = 128; o > 0; o >>= 1) {
        if (threadIdx.x < o) red[threadIdx.x] += red[threadIdx.x + o];
        __syncthreads();
    }
    float rs = rsqrtf(red[0] * (1.0f/DD) + 1e-6f);
    float4 wv = *reinterpret_cast<const float4*>(&w[d4]);
    float4 gv = *reinterpret_cast<const float4*>(&gamma[b*DD + d4]);
    float4 bv = *reinterpret_cast<const float4*>(&beta[b*DD + d4]);
    float4 o4;
    o4.x = f2tf_f(wv.x * v.x * rs * (gv.x + 1.0f) + bv.x);
    o4.y = f2tf_f(wv.y * v.y * rs * (gv.y + 1.0f) + bv.y);
    o4.z = f2tf_f(wv.z * v.z * rs * (gv.z + 1.0f) + bv.z);
    o4.w = f2tf_f(wv.w * v.w * rs * (gv.w + 1.0f) + bv.w);
    *reinterpret_cast<float4*>(&yr[d4]) = o4;
}

// ---------------- TF32 tensor-core GEMM, both operands K-major, pre-rounded ----------------
// C[M,N] = A[M,K] @ Bt[N,K]^T (+Res). M,N % 128 == 0, K % 16 == 0.
#define GBM 128
#define GBN 128
#define GBK 16

__global__ __launch_bounds__(256) void gemm_tf32_kernel(int M, int N, int K,
    const float* __restrict__ A, const float* __restrict__ Bt,
    const float* __restrict__ Res, float* __restrict__ C)
{
    __shared__ float As[2][GBM][GBK+4];   // K-major, +4 pad
    __shared__ float Bs[2][GBN][GBK+4];   // K-major, +4 pad

    int tid = threadIdx.x;
    int wid = tid >> 5, lane = tid & 31;
    int wm = wid >> 2, wn = wid & 3;      // warps 2 x 4 -> warp tile 64 x 32

    const float* Ag = A  + (size_t)blockIdx.y * GBM * K;
    const float* Bg = Bt + (size_t)blockIdx.x * GBN * K;
    float* Cg = C + (size_t)blockIdx.y * GBM * N + blockIdx.x * GBN;
    const float* Rg = Res ? Res + (size_t)blockIdx.y * GBM * N + blockIdx.x * GBN : nullptr;

    float acc[4][4][4];
    #pragma unroll
    for (int i = 0; i < 4; i++)
        #pragma unroll
        for (int j = 0; j < 4; j++)
            #pragma unroll
            for (int r = 0; r < 4; r++) acc[i][j][r] = 0.f;

    int ldr = tid >> 2, ldc = (tid & 3) * 4;   // rows 0-63 (+64), 16B col

    #define LOAD_STAGE(buf, kt) do { \
        asm volatile("cp.async.cg.shared.global [%0], [%1], 16;\n" \
            :: "r"(smem_u32(&As[buf][ldr][ldc])),    "l"(Ag + (size_t)ldr*K + (kt) + ldc)); \
        asm volatile("cp.async.cg.shared.global [%0], [%1], 16;\n" \
            :: "r"(smem_u32(&As[buf][ldr+64][ldc])), "l"(Ag + (size_t)(ldr+64)*K + (kt) + ldc)); \
        asm volatile("cp.async.cg.shared.global [%0], [%1], 16;\n" \
            :: "r"(smem_u32(&Bs[buf][ldr][ldc])),    "l"(Bg + (size_t)ldr*K + (kt) + ldc)); \
        asm volatile("cp.async.cg.shared.global [%0], [%1], 16;\n" \
            :: "r"(smem_u32(&Bs[buf][ldr+64][ldc])), "l"(Bg + (size_t)(ldr+64)*K + (kt) + ldc)); \
        asm volatile("cp.async.commit_group;\n"); \
    } while (0)

    int nk = K / GBK;
    LOAD_STAGE(0, 0);

    for (int t = 0; t < nk; t++) {
        if (t + 1 < nk) LOAD_STAGE((t+1) & 1, (t+1) * GBK);
        else            asm volatile("cp.async.commit_group;\n");
        asm volatile("cp.async.wait_group 1;\n");
        __syncthreads();

        int buf = t & 1;
        #pragma unroll
        for (int kk = 0; kk < 2; kk++) {
            int k0 = kk * 8;
            unsigned af[4][4];
            unsigned bf[2][4];
            // A fragments: 4 x ldmatrix.x4 (m-halves x k-halves), pre-rounded -> no cvt
            #pragma unroll
            for (int i = 0; i < 4; i++) {
                int m = wm*64 + i*16 + (lane & 7) + ((lane >> 3) & 1) * 8;
                int kc = k0 + (lane >> 4) * 4;
                asm volatile("ldmatrix.sync.aligned.m8n8.x4.shared.b16 {%0,%1,%2,%3}, [%4];\n"
                    : "=r"(af[i][0]), "=r"(af[i][1]), "=r"(af[i][2]), "=r"(af[i][3])
                    : "r"(smem_u32(&As[buf][m][kc])));
            }
            // B fragments: 2 x ldmatrix.x4, each covering two n-blocks x two k-halves
            #pragma unroll
            for (int jb = 0; jb < 2; jb++) {
                int n = wn*32 + jb*16 + ((lane >> 4) & 1) * 8 + (lane & 7);
                int kc = k0 + ((lane >> 3) & 1) * 4;
                asm volatile("ldmatrix.sync.aligned.m8n8.x4.shared.b16 {%0,%1,%2,%3}, [%4];\n"
                    : "=r"(bf[jb][0]), "=r"(bf[jb][1]), "=r"(bf[jb][2]), "=r"(bf[jb][3])
                    : "r"(smem_u32(&Bs[buf][n][kc])));
            }
            #pragma unroll
            for (int i = 0; i < 4; i++)
                #pragma unroll
                for (int j = 0; j < 4; j++) {
                    int jb = j >> 1, p = (j & 1) * 2;
                    asm volatile(
                        "mma.sync.aligned.m16n8k8.row.col.f32.tf32.tf32.f32 "
                        "{%0,%1,%2,%3}, {%4,%5,%6,%7}, {%8,%9}, {%0,%1,%2,%3};\n"
                        : "+f"(acc[i][j][0]), "+f"(acc[i][j][1]), "+f"(acc[i][j][2]), "+f"(acc[i][j][3])
                        : "r"(af[i][0]), "r"(af[i][1]), "r"(af[i][2]), "r"(af[i][3]),
                          "r"(bf[jb][p]), "r"(bf[jb][p+1]));
                }
        }
        __syncthreads();
    }
    #undef LOAD_STAGE

    #pragma unroll
    for (int i = 0; i < 4; i++) {
        int r0 = wm*64 + i*16 + (lane >> 2);
        int r1 = r0 + 8;
        #pragma unroll
        for (int j = 0; j < 4; j++) {
            int c0 = wn*32 + j*8 + (lane & 3) * 2;
            float v0 = acc[i][j][0], v1 = acc[i][j][1];
            float v2 = acc[i][j][2], v3 = acc[i][j][3];
            if (Rg) {
                v0 += Rg[(size_t)r0*N + c0];   v1 += Rg[(size_t)r0*N + c0+1];
                v2 += Rg[(size_t)r1*N + c0];   v3 += Rg[(size_t)r1*N + c0+1];
            }
            Cg[(size_t)r0*N + c0]   = v0;  Cg[(size_t)r0*N + c0+1] = v1;
            Cg[(size_t)r1*N + c0]   = v2;  Cg[(size_t)r1*N + c0+1] = v3;
        }
    }
}

// ---------------- fused flash attention (tf32 mma.sync) ----------------
struct FlashSmem {
    float Qs[64][68];
    float Ks[64][68];
    float Vs[64][68];
    float Ps[4][16][72];
    float Sb[128];
};

__global__ __launch_bounds__(128) void flash_attn_kernel(const int* __restrict__ mask)
{
    extern __shared__ char fa_smem_raw[];
    FlashSmem& S = *reinterpret_cast<FlashSmem*>(fa_smem_raw);

    int qt = blockIdx.x, bh = blockIdx.y;
    int b = bh / HH, h = bh % HH;
    int q0 = qt * 64;
    int tid = threadIdx.x, wid = tid >> 5, lane = tid & 31;
    int lq = lane >> 2, lk = lane & 3;

    for (int i = tid; i < 64*16; i += 128) {
        int r = i >> 4, c4 = (i & 15) * 4;
        float4 v = *reinterpret_cast<const float4*>(&g_q[(size_t)(b*TT + q0 + r)*DD + h*DHH + c4]);
        S.Qs[r][c4+0] = v.x * 0.125f; S.Qs[r][c4+1] = v.y * 0.125f;
        S.Qs[r][c4+2] = v.z * 0.125f; S.Qs[r][c4+3] = v.w * 0.125f;
    }

    float o[8][4];
    #pragma unroll
    for (int n = 0; n < 8; n++)
        #pragma unroll
        for (int r = 0; r < 4; r++) o[n][r] = 0.f;
    float mrow[2] = { -3.0e38f, -3.0e38f };
    float lrow[2] = { 0.f, 0.f };

    int qrel = wid*16 + lq;

    for (int kt0 = 0; kt0 < TT; kt0 += 64) {
        __syncthreads();
        for (int i = tid; i < 64*16; i += 128) {
            int r = i >> 4, c4 = (i & 15) * 4;
            float4 kv = *reinterpret_cast<const float4*>(&g_k[(size_t)(b*TT + kt0 + r)*DD + h*DHH + c4]);
            S.Ks[r][c4+0] = kv.x; S.Ks[r][c4+1] = kv.y; S.Ks[r][c4+2] = kv.z; S.Ks[r][c4+3] = kv.w;
            float4 vv = *reinterpret_cast<const float4*>(&g_v[(size_t)(b*TT + kt0 + r)*DD + h*DHH + c4]);
            S.Vs[r][c4+0] = vv.x; S.Vs[r][c4+1] = vv.y; S.Vs[r][c4+2] = vv.z; S.Vs[r][c4+3] = vv.w;
        }
        if (tid < 127) S.Sb[tid] = g_biasrel[h*2048 + (kt0 - q0 + 960) + tid];
        __syncthreads();

        float sacc[8][4];
        #pragma unroll
        for (int n = 0; n < 8; n++)
            #pragma unroll
            for (int r = 0; r < 4; r++) sacc[n][r] = 0.f;

        #pragma unroll
        for (int ks = 0; ks < 8; ks++) {
            int kc = ks*8 + lk;
            unsigned aq[4];
            aq[0] = f2tf(S.Qs[qrel  ][kc  ]);
            aq[1] = f2tf(S.Qs[qrel+8][kc  ]);
            aq[2] = f2tf(S.Qs[qrel  ][kc+4]);
            aq[3] = f2tf(S.Qs[qrel+8][kc+4]);
            #pragma unroll
            for (int n = 0; n < 8; n++) {
                unsigned bk0 = f2tf(S.Ks[n*8 + lq][kc  ]);
                unsigned bk1 = f2tf(S.Ks[n*8 + lq][kc+4]);
                asm volatile(
                    "mma.sync.aligned.m16n8k8.row.col.f32.tf32.tf32.f32 "
                    "{%0,%1,%2,%3}, {%4,%5,%6,%7}, {%8,%9}, {%0,%1,%2,%3};\n"
                    : "+f"(sacc[n][0]), "+f"(sacc[n][1]), "+f"(sacc[n][2]), "+f"(sacc[n][3])
                    : "r"(aq[0]), "r"(aq[1]), "r"(aq[2]), "r"(aq[3]), "r"(bk0), "r"(bk1));
            }
        }

        float mnew[2] = { mrow[0], mrow[1] };
        #pragma unroll
        for (int n = 0; n < 8; n++) {
            #pragma unroll
            for (int e = 0; e < 2; e++) {
                int qr = qrel + e*8;
                const int* mrowp = mask + ((size_t)(b*TT + q0 + qr))*TT + kt0;
                #pragma unroll
                for (int c = 0; c < 2; c++) {
                    int kr = n*8 + 2*lk + c;
                    float s = sacc[n][e*2+c] + S.Sb[kr - qr + 63];
                    if (mrowp[kr] == 0) s = -1e9f;
                    sacc[n][e*2+c] = s;
                    mnew[e] = fmaxf(mnew[e], s);
                }
            }
        }
        #pragma unroll
        for (int e = 0; e < 2; e++) {
            mnew[e] = fmaxf(mnew[e], __shfl_xor_sync(0xffffffffu, mnew[e], 1));
            mnew[e] = fmaxf(mnew[e], __shfl_xor_sync(0xffffffffu, mnew[e], 2));
        }
        float alpha[2], rs[2] = {0.f, 0.f};
        alpha[0] = __expf(mrow[0] - mnew[0]);
        alpha[1] = __expf(mrow[1] - mnew[1]);
        mrow[0] = mnew[0]; mrow[1] = mnew[1];

        #pragma unroll
        for (int n = 0; n < 8; n++) {
            #pragma unroll
            for (int e = 0; e < 2; e++) {
                float p0 = __expf(sacc[n][e*2+0] - mnew[e]);
                float p1 = __expf(sacc[n][e*2+1] - mnew[e]);
                rs[e] += p0 + p1;
                float2 pv;
                pv.x = __uint_as_float(f2tf(p0));
                pv.y = __uint_as_float(f2tf(p1));
                *reinterpret_cast<float2*>(&S.Ps[wid][lq + e*8][n*8 + 2*lk]) = pv;
            }
        }
        #pragma unroll
        for (int e = 0; e < 2; e++) {
            rs[e] += __shfl_xor_sync(0xffffffffu, rs[e], 1);
            rs[e] += __shfl_xor_sync(0xffffffffu, rs[e], 2);
            lrow[e] = lrow[e] * alpha[e] + rs[e];
        }
        #pragma unroll
        for (int n = 0; n < 8; n++) {
            o[n][0] *= alpha[0]; o[n][1] *= alpha[0];
            o[n][2] *= alpha[1]; o[n][3] *= alpha[1];
        }
        __syncwarp();

        #pragma unroll
        for (int ks = 0; ks < 8; ks++) {
            int kc = ks*8 + lk;
            unsigned ap[4];
            ap[0] = __float_as_uint(S.Ps[wid][lq  ][kc  ]);
            ap[1] = __float_as_uint(S.Ps[wid][lq+8][kc  ]);
            ap[2] = __float_as_uint(S.Ps[wid][lq  ][kc+4]);
            ap[3] = __float_as_uint(S.Ps[wid][lq+8][kc+4]);
            #pragma unroll
            for (int n = 0; n < 8; n++) {
                unsigned bv0 = f2tf(S.Vs[kc  ][n*8 + lq]);
                unsigned bv1 = f2tf(S.Vs[kc+4][n*8 + lq]);
                asm volatile(
                    "mma.sync.aligned.m16n8k8.row.col.f32.tf32.tf32.f32 "
                    "{%0,%1,%2,%3}, {%4,%5,%6,%7}, {%8,%9}, {%0,%1,%2,%3};\n"
                    : "+f"(o[n][0]), "+f"(o[n][1]), "+f"(o[n][2]), "+f"(o[n][3])
                    : "r"(ap[0]), "r"(ap[1]), "r"(ap[2]), "r"(ap[3]), "r"(bv0), "r"(bv1));
            }
        }
        __syncwarp();
    }

    float inv0 = 1.0f / lrow[0], inv1 = 1.0f / lrow[1];
    #pragma unroll
    for (int e = 0; e < 2; e++) {
        int qg = b*TT + q0 + qrel + e*8;
        float inv = e ? inv1 : inv0;
        #pragma unroll
        for (int n = 0; n < 8; n++) {
            float2 w;
            w.x = f2tf_f(o[n][e*2+0] * inv);
            w.y = f2tf_f(o[n][e*2+1] * inv);
            *reinterpret_cast<float2*>(&g_ctx[(size_t)qg*DD + h*DHH + n*8 + 2*lk]) = w;
        }
    }
}

// ---------------- GEGLU (tf32-rounded output) ----------------
__global__ void geglu_kernel()
{
    size_t idx = (size_t)blockIdx.x * blockDim.x + threadIdx.x;
    if (idx >= (size_t)BT * 2 * DD) return;
    size_t r = idx / (2*DD);
    int c = (int)(idx % (2*DD));
    float p1 = g_ffn1[r * 4*DD + c];
    float p2 = g_ffn1[r * 4*DD + 2*DD + c];
    float gelu = 0.5f * p2 * (1.0f + erff(p2 * 0.70710678118654752f));
    g_gg[idx] = f2tf_f(p1 * gelu);
}

// ---------------- host launcher ----------------
extern "C" void kernel_launch(void* const* d_in, const int* in_sizes, int n_in,
                              void* d_out, int out_size)
{
    const float* x       = (const float*)d_in[0];
    const int*   mask    = (const int*)  d_in[1];
    const float* cond    = (const float*)d_in[2];
    const float* norm1_w = (const float*)d_in[3];
    const float* f1gw    = (const float*)d_in[4];
    const float* f1gb    = (const float*)d_in[5];
    const float* f1bw    = (const float*)d_in[6];
    const float* f1bb    = (const float*)d_in[7];
    const float* wq      = (const float*)d_in[8];
    const float* wk      = (const float*)d_in[9];
    const float* wv      = (const float*)d_in[10];
    const float* wo      = (const float*)d_in[11];
    const float* rel_emb = (const float*)d_in[12];
    const float* norm3_w = (const float*)d_in[13];
    const float* f3gw    = (const float*)d_in[14];
    const float* f3gb    = (const float*)d_in[15];
    const float* f3bw    = (const float*)d_in[16];
    const float* f3bb    = (const float*)d_in[17];
    const float* w1      = (const float*)d_in[18];
    const float* w2      = (const float*)d_in[19];
    float* out = (float*)d_out;
    float* outbias = (out_size >= BTD + BIAS_ELEMS) ? out + BTD : nullptr;

    float *p_y, *p_q, *p_k, *p_v, *p_ctx, *p_x1, *p_ffn1, *p_gg;
    float *p_g1, *p_b1, *p_g3, *p_b3;
    float *p_wqT, *p_wkT, *p_wvT, *p_woT, *p_w1T, *p_w2T;
    cudaGetSymbolAddress((void**)&p_g1, g_gamma1);
    cudaGetSymbolAddress((void**)&p_b1, g_beta1);
    cudaGetSymbolAddress((void**)&p_g3, g_gamma3);
    cudaGetSymbolAddress((void**)&p_b3, g_beta3);
    cudaGetSymbolAddress((void**)&p_y,  g_y);
    cudaGetSymbolAddress((void**)&p_q,  g_q);
    cudaGetSymbolAddress((void**)&p_k,  g_k);
    cudaGetSymbolAddress((void**)&p_v,  g_v);
    cudaGetSymbolAddress((void**)&p_ctx, g_ctx);
    cudaGetSymbolAddress((void**)&p_x1, g_x1);
    cudaGetSymbolAddress((void**)&p_ffn1, g_ffn1);
    cudaGetSymbolAddress((void**)&p_gg, g_gg);
    cudaGetSymbolAddress((void**)&p_wqT, g_wqT);
    cudaGetSymbolAddress((void**)&p_wkT, g_wkT);
    cudaGetSymbolAddress((void**)&p_wvT, g_wvT);
    cudaGetSymbolAddress((void**)&p_woT, g_woT);
    cudaGetSymbolAddress((void**)&p_w1T, g_w1T);
    cudaGetSymbolAddress((void**)&p_w2T, g_w2T);

    cudaFuncSetAttribute(flash_attn_kernel,
                         cudaFuncAttributeMaxDynamicSharedMemorySize,
                         (int)sizeof(FlashSmem));

    // 0) transpose + tf32-round weights (K-major)
    dim3 tb(32, 8);
    transpose_tf32_kernel<<<dim3(DD/32, DD/32), tb>>>(wq, p_wqT, DD, DD);
    transpose_tf32_kernel<<<dim3(DD/32, DD/32), tb>>>(wk, p_wkT, DD, DD);
    transpose_tf32_kernel<<<dim3(DD/32, DD/32), tb>>>(wv, p_wvT, DD, DD);
    transpose_tf32_kernel<<<dim3(DD/32, DD/32), tb>>>(wo, p_woT, DD, DD);
    transpose_tf32_kernel<<<dim3(4*DD/32, DD/32), tb>>>(w1, p_w1T, DD, 4*DD);
    transpose_tf32_kernel<<<dim3(DD/32, 2*DD/32), tb>>>(w2, p_w2T, 2*DD, DD);

    // 1) FiLM params + bias LUT + bias output
    film_params_kernel<<<(BB*DD + 255)/256, 256>>>(cond, f1gw, f1gb, f1bw, f1bb,
                                                   f3gw, f3gb, f3bw, f3bb);
    biasrel_kernel<<<(2047 + 255)/256, 256>>>(rel_emb);
    if (outbias)
        bias_out_kernel<<<(TT*TT + 255)/256, 256>>>(rel_emb, outbias);

    // 2) y = film(rmsnorm(x))  (tf32-rounded)
    rmsnorm_film_kernel<<<BT, 256>>>(x, norm1_w, p_g1, p_b1, p_y);

    // 3) Q/K/V projections
    dim3 gproj(DD/GBN, BT/GBM);
    gemm_tf32_kernel<<<gproj, 256>>>(BT, DD, DD, p_y, p_wqT, nullptr, p_q);
    gemm_tf32_kernel<<<gproj, 256>>>(BT, DD, DD, p_y, p_wkT, nullptr, p_k);
    gemm_tf32_kernel<<<gproj, 256>>>(BT, DD, DD, p_y, p_wvT, nullptr, p_v);

    // 4) fused flash attention -> g_ctx (tf32-rounded)
    flash_attn_kernel<<<dim3(TT/64, BB*HH), 128, sizeof(FlashSmem)>>>(mask);

    // 5) output projection + residual -> x1
    gemm_tf32_kernel<<<gproj, 256>>>(BT, DD, DD, p_ctx, p_woT, x, p_x1);

    // 6) y2 = film3(rmsnorm(x1)) (tf32-rounded)
    rmsnorm_film_kernel<<<BT, 256>>>(p_x1, norm3_w, p_g3, p_b3, p_y);

    // 7) FFN
    gemm_tf32_kernel<<<dim3(4*DD/GBN, BT/GBM), 256>>>(BT, 4*DD, DD, p_y, p_w1T, nullptr, p_ffn1);
    geglu_kernel<<<(int)(((size_t)BT*2*DD + 255)/256), 256>>>();
    gemm_tf32_kernel<<<dim3(DD/GBN, BT/GBM), 256>>>(BT, DD, 2*DD, p_gg, p_w2T, p_x1, out);
}

// round 11
// speedup vs baseline: 3.8435x; 1.3545x over previous
#include <cuda_runtime.h>
#include <cuda_fp16.h>
#include <math.h>

#define BB 4
#define TT 1024
#define DD 1024
#define HH 16
#define DHH 64
#define DCC 64
#define BT (BB*TT)        // 4096
#define BTD (BB*TT*DD)    // 4194304
#define BIAS_ELEMS (HH*TT*TT) // 16777216

// ---------------- scratch (device globals; no allocation) ----------------
__device__ float g_gamma1[BB*DD];
__device__ float g_beta1 [BB*DD];
__device__ float g_gamma3[BB*DD];
__device__ float g_beta3 [BB*DD];
__device__ float g_q   [BTD];
__device__ float g_k   [BTD];
__device__ float g_v   [BTD];
__device__ float g_x1  [BTD];
__device__ float g_biasrel[HH*2048];
__device__ float g_ffn1[(size_t)BT*4*DD];
// fp16 activation/weight buffers (GEMM operands)
__device__ __half g_y_h  [BTD];
__device__ __half g_ctx_h[BTD];
__device__ __half g_gg_h [(size_t)BT*2*DD];
__device__ __half g_wqT[DD*DD];
__device__ __half g_wkT[DD*DD];
__device__ __half g_wvT[DD*DD];
__device__ __half g_woT[DD*DD];
__device__ __half g_w1T[(size_t)4*DD*DD];
__device__ __half g_w2T[(size_t)2*DD*DD];

__device__ __forceinline__ unsigned smem_u32(const void* p) {
    return (unsigned)__cvta_generic_to_shared(p);
}
__device__ __forceinline__ unsigned f2tf(float f) {
    unsigned u;
    asm("cvt.rna.tf32.f32 %0, %1;\n" : "=r"(u) : "f"(f));
    return u;
}

// ---------------- FiLM params ----------------
__global__ void film_params_kernel(const float* __restrict__ cond,
    const float* __restrict__ g1w, const float* __restrict__ g1b,
    const float* __restrict__ b1w, const float* __restrict__ b1b,
    const float* __restrict__ g3w, const float* __restrict__ g3b,
    const float* __restrict__ b3w, const float* __restrict__ b3b)
{
    int idx = blockIdx.x * blockDim.x + threadIdx.x;
    if (idx >= BB*DD) return;
    int b = idx / DD, d = idx % DD;
    float s1 = 0.f, s2 = 0.f, s3 = 0.f, s4 = 0.f;
    #pragma unroll 8
    for (int c = 0; c < DCC; c++) {
        float cv = cond[b*DCC + c];
        s1 += cv * g1w[c*DD + d];
        s2 += cv * b1w[c*DD + d];
        s3 += cv * g3w[c*DD + d];
        s4 += cv * b3w[c*DD + d];
    }
    g_gamma1[idx] = s1 + g1b[d];
    g_beta1 [idx] = s2 + b1b[d];
    g_gamma3[idx] = s3 + g3b[d];
    g_beta3 [idx] = s4 + b3b[d];
}

// ---------------- T5 bucket ----------------
__device__ __forceinline__ int t5_bucket(int rp) {
    int bucket = (rp > 0) ? 16 : 0;
    int arp = rp < 0 ? -rp : rp;
    int off;
    if (arp < 8) {
        off = arp;
    } else {
        float l = logf((float)arp * 0.125f) / logf(16.0f) * 8.0f;
        off = 8 + (int)l;
        if (off > 15) off = 15;
    }
    return bucket + off;
}

__global__ void biasrel_kernel(const float* __restrict__ rel_emb)
{
    int idx = blockIdx.x * blockDim.x + threadIdx.x;
    if (idx >= 2047) return;
    int bucket = t5_bucket(idx - 1023);
    #pragma unroll
    for (int h = 0; h < HH; h++)
        g_biasrel[h*2048 + idx] = rel_emb[bucket*HH + h];
}

__global__ void bias_out_kernel(const float* __restrict__ rel_emb, float* __restrict__ outbias)
{
    int idx = blockIdx.x * blockDim.x + threadIdx.x;
    if (idx >= TT*TT) return;
    int q = idx / TT, k = idx % TT;
    int bucket = t5_bucket(k - q);
    #pragma unroll
    for (int h = 0; h < HH; h++)
        outbias[(size_t)h*TT*TT + idx] = rel_emb[bucket*HH + h];
}

// ---------------- weight transpose -> half K-major: src[K][N] -> dst[N][K] ----------------
__global__ void transpose_h_kernel(const float* __restrict__ src, __half* __restrict__ dst,
                                   int Kd, int Nd)
{
    __shared__ float ts[32][33];
    int n0 = blockIdx.x*32, k0 = blockIdx.y*32;
    int tx = threadIdx.x, ty = threadIdx.y;   // 32 x 8
    #pragma unroll
    for (int i = 0; i < 32; i += 8)
        ts[ty+i][tx] = src[(size_t)(k0+ty+i)*Nd + n0+tx];
    __syncthreads();
    #pragma unroll
    for (int i = 0; i < 32; i += 8)
        dst[(size_t)(n0+ty+i)*Kd + k0+tx] = __float2half_rn(ts[tx][ty+i]);
}

// ---------------- RMSNorm + FiLM (float4 in, half out) ----------------
__global__ void rmsnorm_film_kernel(const float* __restrict__ x, const float* __restrict__ w,
                                    const float* __restrict__ gamma, const float* __restrict__ beta,
                                    __half* __restrict__ y)
{
    int row = blockIdx.x;
    int b = row / TT;
    const float* xr = x + (size_t)row * DD;
    __half* yr = y + (size_t)row * DD;
    int d4 = threadIdx.x * 4;
    float4 v = *reinterpret_cast<const float4*>(&xr[d4]);
    float s = v.x*v.x + v.y*v.y + v.z*v.z + v.w*v.w;
    __shared__ float red[256];
    red[threadIdx.x] = s; __syncthreads();
    for (int o = 128; o > 0; o >>= 1) {
        if (threadIdx.x < o) red[threadIdx.x] += red[threadIdx.x + o];
        __syncthreads();
    }
    float rs = rsqrtf(red[0] * (1.0f/DD) + 1e-6f);
    float4 wv = *reinterpret_cast<const float4*>(&w[d4]);
    float4 gv = *reinterpret_cast<const float4*>(&gamma[b*DD + d4]);
    float4 bv = *reinterpret_cast<const float4*>(&beta[b*DD + d4]);
    __half2 h0 = __floats2half2_rn(wv.x * v.x * rs * (gv.x + 1.0f) + bv.x,
                                   wv.y * v.y * rs * (gv.y + 1.0f) + bv.y);
    __half2 h1 = __floats2half2_rn(wv.z * v.z * rs * (gv.z + 1.0f) + bv.z,
                                   wv.w * v.w * rs * (gv.w + 1.0f) + bv.w);
    *reinterpret_cast<__half2*>(&yr[d4])   = h0;
    *reinterpret_cast<__half2*>(&yr[d4+2]) = h1;
}

// ---------------- FP16 tensor-core GEMM, both operands K-major half ----------------
// C[M,N] = A[M,K] @ Bt[N,K]^T (+Res fp32). M,N % 128 == 0, K % 32 == 0.
#define GBM 128
#define GBN 128
#define GBK 32
#define HPAD 8   // halves -> row stride 80 B

__global__ __launch_bounds__(256) void gemm_f16_kernel(int M, int N, int K,
    const __half* __restrict__ A, const __half* __restrict__ Bt,
    const float* __restrict__ Res, float* __restrict__ C)
{
    __shared__ __half As[2][GBM][GBK+HPAD];
    __shared__ __half Bs[2][GBN][GBK+HPAD];

    int tid = threadIdx.x;
    int wid = tid >> 5, lane = tid & 31;
    int wm = wid >> 2, wn = wid & 3;      // 2 x 4 warps -> warp tile 64 x 32

    const __half* Ag = A  + (size_t)blockIdx.y * GBM * K;
    const __half* Bg = Bt + (size_t)blockIdx.x * GBN * K;
    float* Cg = C + (size_t)blockIdx.y * GBM * N + blockIdx.x * GBN;
    const float* Rg = Res ? Res + (size_t)blockIdx.y * GBM * N + blockIdx.x * GBN : nullptr;

    float acc[4][4][4];
    #pragma unroll
    for (int i = 0; i < 4; i++)
        #pragma unroll
        for (int j = 0; j < 4; j++)
            #pragma unroll
            for (int r = 0; r < 4; r++) acc[i][j][r] = 0.f;

    int lr = tid >> 2, lc = (tid & 3) * 8;   // 64B rows in 4x16B chunks

    #define LOAD_STAGE(buf, kt) do { \
        asm volatile("cp.async.cg.shared.global [%0], [%1], 16;\n" \
            :: "r"(smem_u32(&As[buf][lr][lc])),    "l"(Ag + (size_t)lr*K + (kt) + lc)); \
        asm volatile("cp.async.cg.shared.global [%0], [%1], 16;\n" \
            :: "r"(smem_u32(&As[buf][lr+64][lc])), "l"(Ag + (size_t)(lr+64)*K + (kt) + lc)); \
        asm volatile("cp.async.cg.shared.global [%0], [%1], 16;\n" \
            :: "r"(smem_u32(&Bs[buf][lr][lc])),    "l"(Bg + (size_t)lr*K + (kt) + lc)); \
        asm volatile("cp.async.cg.shared.global [%0], [%1], 16;\n" \
            :: "r"(smem_u32(&Bs[buf][lr+64][lc])), "l"(Bg + (size_t)(lr+64)*K + (kt) + lc)); \
        asm volatile("cp.async.commit_group;\n"); \
    } while (0)

    int nk = K / GBK;
    LOAD_STAGE(0, 0);

    for (int t = 0; t < nk; t++) {
        if (t + 1 < nk) LOAD_STAGE((t+1) & 1, (t+1) * GBK);
        else            asm volatile("cp.async.commit_group;\n");
        asm volatile("cp.async.wait_group 1;\n");
        __syncthreads();

        int buf = t & 1;
        #pragma unroll
        for (int kk = 0; kk < 2; kk++) {
            int k0 = kk * 16;
            int kc = k0 + (lane >> 4) * 8;
            unsigned af[4][4];
            unsigned bf[2][4];
            // A fragments: 16 m-rows x 16 k each via ldmatrix.x4
            #pragma unroll
            for (int i = 0; i < 4; i++) {
                int m = wm*64 + i*16 + (lane & 15);
                asm volatile("ldmatrix.sync.aligned.m8n8.x4.shared.b16 {%0,%1,%2,%3}, [%4];\n"
                    : "=r"(af[i][0]), "=r"(af[i][1]), "=r"(af[i][2]), "=r"(af[i][3])
                    : "r"(smem_u32(&As[buf][m][kc])));
            }
            // B fragments: 16 n-rows x 16 k each via ldmatrix.x4
            #pragma unroll
            for (int jb = 0; jb < 2; jb++) {
                int n = wn*32 + jb*16 + (lane & 15);
                asm volatile("ldmatrix.sync.aligned.m8n8.x4.shared.b16 {%0,%1,%2,%3}, [%4];\n"
                    : "=r"(bf[jb][0]), "=r"(bf[jb][1]), "=r"(bf[jb][2]), "=r"(bf[jb][3])
                    : "r"(smem_u32(&Bs[buf][n][kc])));
            }
            #pragma unroll
            for (int i = 0; i < 4; i++)
                #pragma unroll
                for (int j = 0; j < 4; j++) {
                    int jb = j >> 1, p = j & 1;
                    asm volatile(
                        "mma.sync.aligned.m16n8k16.row.col.f32.f16.f16.f32 "
                        "{%0,%1,%2,%3}, {%4,%5,%6,%7}, {%8,%9}, {%0,%1,%2,%3};\n"
                        : "+f"(acc[i][j][0]), "+f"(acc[i][j][1]), "+f"(acc[i][j][2]), "+f"(acc[i][j][3])
                        : "r"(af[i][0]), "r"(af[i][1]), "r"(af[i][2]), "r"(af[i][3]),
                          "r"(bf[jb][p]), "r"(bf[jb][p+2]));
                }
        }
        __syncthreads();
    }
    #undef LOAD_STAGE

    #pragma unroll
    for (int i = 0; i < 4; i++) {
        int r0 = wm*64 + i*16 + (lane >> 2);
        int r1 = r0 + 8;
        #pragma unroll
        for (int j = 0; j < 4; j++) {
            int c0 = wn*32 + j*8 + (lane & 3) * 2;
            float v0 = acc[i][j][0], v1 = acc[i][j][1];
            float v2 = acc[i][j][2], v3 = acc[i][j][3];
            if (Rg) {
                v0 += Rg[(size_t)r0*N + c0];   v1 += Rg[(size_t)r0*N + c0+1];
                v2 += Rg[(size_t)r1*N + c0];   v3 += Rg[(size_t)r1*N + c0+1];
            }
            Cg[(size_t)r0*N + c0]   = v0;  Cg[(size_t)r0*N + c0+1] = v1;
            Cg[(size_t)r1*N + c0]   = v2;  Cg[(size_t)r1*N + c0+1] = v3;
        }
    }
}

// ---------------- fused flash attention (tf32 mma.sync, half ctx output) ----------------
struct FlashSmem {
    float Qs[64][68];
    float Ks[64][68];
    float Vs[64][68];
    float Ps[4][16][72];
    float Sb[128];
};

__global__ __launch_bounds__(128) void flash_attn_kernel(const int* __restrict__ mask)
{
    extern __shared__ char fa_smem_raw[];
    FlashSmem& S = *reinterpret_cast<FlashSmem*>(fa_smem_raw);

    int qt = blockIdx.x, bh = blockIdx.y;
    int b = bh / HH, h = bh % HH;
    int q0 = qt * 64;
    int tid = threadIdx.x, wid = tid >> 5, lane = tid & 31;
    int lq = lane >> 2, lk = lane & 3;

    for (int i = tid; i < 64*16; i += 128) {
        int r = i >> 4, c4 = (i & 15) * 4;
        float4 v = *reinterpret_cast<const float4*>(&g_q[(size_t)(b*TT + q0 + r)*DD + h*DHH + c4]);
        S.Qs[r][c4+0] = v.x * 0.125f; S.Qs[r][c4+1] = v.y * 0.125f;
        S.Qs[r][c4+2] = v.z * 0.125f; S.Qs[r][c4+3] = v.w * 0.125f;
    }

    float o[8][4];
    #pragma unroll
    for (int n = 0; n < 8; n++)
        #pragma unroll
        for (int r = 0; r < 4; r++) o[n][r] = 0.f;
    float mrow[2] = { -3.0e38f, -3.0e38f };
    float lrow[2] = { 0.f, 0.f };

    int qrel = wid*16 + lq;

    for (int kt0 = 0; kt0 < TT; kt0 += 64) {
        __syncthreads();
        for (int i = tid; i < 64*16; i += 128) {
            int r = i >> 4, c4 = (i & 15) * 4;
            float4 kv = *reinterpret_cast<const float4*>(&g_k[(size_t)(b*TT + kt0 + r)*DD + h*DHH + c4]);
            S.Ks[r][c4+0] = kv.x; S.Ks[r][c4+1] = kv.y; S.Ks[r][c4+2] = kv.z; S.Ks[r][c4+3] = kv.w;
            float4 vv = *reinterpret_cast<const float4*>(&g_v[(size_t)(b*TT + kt0 + r)*DD + h*DHH + c4]);
            S.Vs[r][c4+0] = vv.x; S.Vs[r][c4+1] = vv.y; S.Vs[r][c4+2] = vv.z; S.Vs[r][c4+3] = vv.w;
        }
        if (tid < 127) S.Sb[tid] = g_biasrel[h*2048 + (kt0 - q0 + 960) + tid];
        __syncthreads();

        float sacc[8][4];
        #pragma unroll
        for (int n = 0; n < 8; n++)
            #pragma unroll
            for (int r = 0; r < 4; r++) sacc[n][r] = 0.f;

        #pragma unroll
        for (int ks = 0; ks < 8; ks++) {
            int kc = ks*8 + lk;
            unsigned aq[4];
            aq[0] = f2tf(S.Qs[qrel  ][kc  ]);
            aq[1] = f2tf(S.Qs[qrel+8][kc  ]);
            aq[2] = f2tf(S.Qs[qrel  ][kc+4]);
            aq[3] = f2tf(S.Qs[qrel+8][kc+4]);
            #pragma unroll
            for (int n = 0; n < 8; n++) {
                unsigned bk0 = f2tf(S.Ks[n*8 + lq][kc  ]);
                unsigned bk1 = f2tf(S.Ks[n*8 + lq][kc+4]);
                asm volatile(
                    "mma.sync.aligned.m16n8k8.row.col.f32.tf32.tf32.f32 "
                    "{%0,%1,%2,%3}, {%4,%5,%6,%7}, {%8,%9}, {%0,%1,%2,%3};\n"
                    : "+f"(sacc[n][0]), "+f"(sacc[n][1]), "+f"(sacc[n][2]), "+f"(sacc[n][3])
                    : "r"(aq[0]), "r"(aq[1]), "r"(aq[2]), "r"(aq[3]), "r"(bk0), "r"(bk1));
            }
        }

        float mnew[2] = { mrow[0], mrow[1] };
        #pragma unroll
        for (int n = 0; n < 8; n++) {
            #pragma unroll
            for (int e = 0; e < 2; e++) {
                int qr = qrel + e*8;
                const int* mrowp = mask + ((size_t)(b*TT + q0 + qr))*TT + kt0;
                #pragma unroll
                for (int c = 0; c < 2; c++) {
                    int kr = n*8 + 2*lk + c;
                    float s = sacc[n][e*2+c] + S.Sb[kr - qr + 63];
                    if (mrowp[kr] == 0) s = -1e9f;
                    sacc[n][e*2+c] = s;
                    mnew[e] = fmaxf(mnew[e], s);
                }
            }
        }
        #pragma unroll
        for (int e = 0; e < 2; e++) {
            mnew[e] = fmaxf(mnew[e], __shfl_xor_sync(0xffffffffu, mnew[e], 1));
            mnew[e] = fmaxf(mnew[e], __shfl_xor_sync(0xffffffffu, mnew[e], 2));
        }
        float alpha[2], rs[2] = {0.f, 0.f};
        alpha[0] = __expf(mrow[0] - mnew[0]);
        alpha[1] = __expf(mrow[1] - mnew[1]);
        mrow[0] = mnew[0]; mrow[1] = mnew[1];

        #pragma unroll
        for (int n = 0; n < 8; n++) {
            #pragma unroll
            for (int e = 0; e < 2; e++) {
                float p0 = __expf(sacc[n][e*2+0] - mnew[e]);
                float p1 = __expf(sacc[n][e*2+1] - mnew[e]);
                rs[e] += p0 + p1;
                float2 pv;
                pv.x = __uint_as_float(f2tf(p0));
                pv.y = __uint_as_float(f2tf(p1));
                *reinterpret_cast<float2*>(&S.Ps[wid][lq + e*8][n*8 + 2*lk]) = pv;
            }
        }
        #pragma unroll
        for (int e = 0; e < 2; e++) {
            rs[e] += __shfl_xor_sync(0xffffffffu, rs[e], 1);
            rs[e] += __shfl_xor_sync(0xffffffffu, rs[e], 2);
            lrow[e] = lrow[e] * alpha[e] + rs[e];
        }
        #pragma unroll
        for (int n = 0; n < 8; n++) {
            o[n][0] *= alpha[0]; o[n][1] *= alpha[0];
            o[n][2] *= alpha[1]; o[n][3] *= alpha[1];
        }
        __syncwarp();

        #pragma unroll
        for (int ks = 0; ks < 8; ks++) {
            int kc = ks*8 + lk;
            unsigned ap[4];
            ap[0] = __float_as_uint(S.Ps[wid][lq  ][kc  ]);
            ap[1] = __float_as_uint(S.Ps[wid][lq+8][kc  ]);
            ap[2] = __float_as_uint(S.Ps[wid][lq  ][kc+4]);
            ap[3] = __float_as_uint(S.Ps[wid][lq+8][kc+4]);
            #pragma unroll
            for (int n = 0; n < 8; n++) {
                unsigned bv0 = f2tf(S.Vs[kc  ][n*8 + lq]);
                unsigned bv1 = f2tf(S.Vs[kc+4][n*8 + lq]);
                asm volatile(
                    "mma.sync.aligned.m16n8k8.row.col.f32.tf32.tf32.f32 "
                    "{%0,%1,%2,%3}, {%4,%5,%6,%7}, {%8,%9}, {%0,%1,%2,%3};\n"
                    : "+f"(o[n][0]), "+f"(o[n][1]), "+f"(o[n][2]), "+f"(o[n][3])
                    : "r"(ap[0]), "r"(ap[1]), "r"(ap[2]), "r"(ap[3]), "r"(bv0), "r"(bv1));
            }
        }
        __syncwarp();
    }

    float inv0 = 1.0f / lrow[0], inv1 = 1.0f / lrow[1];
    #pragma unroll
    for (int e = 0; e < 2; e++) {
        int qg = b*TT + q0 + qrel + e*8;
        float inv = e ? inv1 : inv0;
        #pragma unroll
        for (int n = 0; n < 8; n++) {
            __half2 hw = __floats2half2_rn(o[n][e*2+0] * inv, o[n][e*2+1] * inv);
            *reinterpret_cast<__half2*>(&g_ctx_h[(size_t)qg*DD + h*DHH + n*8 + 2*lk]) = hw;
        }
    }
}

// ---------------- GEGLU (half output) ----------------
__global__ void geglu_kernel()
{
    size_t idx = (size_t)blockIdx.x * blockDim.x + threadIdx.x;
    if (idx >= (size_t)BT * 2 * DD) return;
    size_t r = idx / (2*DD);
    int c = (int)(idx % (2*DD));
    float p1 = g_ffn1[r * 4*DD + c];
    float p2 = g_ffn1[r * 4*DD + 2*DD + c];
    float gelu = 0.5f * p2 * (1.0f + erff(p2 * 0.70710678118654752f));
    g_gg_h[idx] = __float2half_rn(p1 * gelu);
}

// ---------------- host launcher ----------------
extern "C" void kernel_launch(void* const* d_in, const int* in_sizes, int n_in,
                              void* d_out, int out_size)
{
    const float* x       = (const float*)d_in[0];
    const int*   mask    = (const int*)  d_in[1];
    const float* cond    = (const float*)d_in[2];
    const float* norm1_w = (const float*)d_in[3];
    const float* f1gw    = (const float*)d_in[4];
    const float* f1gb    = (const float*)d_in[5];
    const float* f1bw    = (const float*)d_in[6];
    const float* f1bb    = (const float*)d_in[7];
    const float* wq      = (const float*)d_in[8];
    const float* wk      = (const float*)d_in[9];
    const float* wv      = (const float*)d_in[10];
    const float* wo      = (const float*)d_in[11];
    const float* rel_emb = (const float*)d_in[12];
    const float* norm3_w = (const float*)d_in[13];
    const float* f3gw    = (const float*)d_in[14];
    const float* f3gb    = (const float*)d_in[15];
    const float* f3bw    = (const float*)d_in[16];
    const float* f3bb    = (const float*)d_in[17];
    const float* w1      = (const float*)d_in[18];
    const float* w2      = (const float*)d_in[19];
    float* out = (float*)d_out;
    float* outbias = (out_size >= BTD + BIAS_ELEMS) ? out + BTD : nullptr;

    float *p_q, *p_k, *p_v, *p_x1, *p_ffn1;
    float *p_g1, *p_b1, *p_g3, *p_b3;
    __half *p_y_h, *p_ctx_h, *p_gg_h;
    __half *p_wqT, *p_wkT, *p_wvT, *p_woT, *p_w1T, *p_w2T;
    cudaGetSymbolAddress((void**)&p_g1, g_gamma1);
    cudaGetSymbolAddress((void**)&p_b1, g_beta1);
    cudaGetSymbolAddress((void**)&p_g3, g_gamma3);
    cudaGetSymbolAddress((void**)&p_b3, g_beta3);
    cudaGetSymbolAddress((void**)&p_q,  g_q);
    cudaGetSymbolAddress((void**)&p_k,  g_k);
    cudaGetSymbolAddress((void**)&p_v,  g_v);
    cudaGetSymbolAddress((void**)&p_x1, g_x1);
    cudaGetSymbolAddress((void**)&p_ffn1, g_ffn1);
    cudaGetSymbolAddress((void**)&p_y_h,  g_y_h);
    cudaGetSymbolAddress((void**)&p_ctx_h, g_ctx_h);
    cudaGetSymbolAddress((void**)&p_gg_h, g_gg_h);
    cudaGetSymbolAddress((void**)&p_wqT, g_wqT);
    cudaGetSymbolAddress((void**)&p_wkT, g_wkT);
    cudaGetSymbolAddress((void**)&p_wvT, g_wvT);
    cudaGetSymbolAddress((void**)&p_woT, g_woT);
    cudaGetSymbolAddress((void**)&p_w1T, g_w1T);
    cudaGetSymbolAddress((void**)&p_w2T, g_w2T);

    cudaFuncSetAttribute(flash_attn_kernel,
                         cudaFuncAttributeMaxDynamicSharedMemorySize,
                         (int)sizeof(FlashSmem));

    // 0) transpose weights -> half K-major
    dim3 tb(32, 8);
    transpose_h_kernel<<<dim3(DD/32, DD/32), tb>>>(wq, p_wqT, DD, DD);
    transpose_h_kernel<<<dim3(DD/32, DD/32), tb>>>(wk, p_wkT, DD, DD);
    transpose_h_kernel<<<dim3(DD/32, DD/32), tb>>>(wv, p_wvT, DD, DD);
    transpose_h_kernel<<<dim3(DD/32, DD/32), tb>>>(wo, p_woT, DD, DD);
    transpose_h_kernel<<<dim3(4*DD/32, DD/32), tb>>>(w1, p_w1T, DD, 4*DD);
    transpose_h_kernel<<<dim3(DD/32, 2*DD/32), tb>>>(w2, p_w2T, 2*DD, DD);

    // 1) FiLM params + bias LUT + bias output
    film_params_kernel<<<(BB*DD + 255)/256, 256>>>(cond, f1gw, f1gb, f1bw, f1bb,
                                                   f3gw, f3gb, f3bw, f3bb);
    biasrel_kernel<<<(2047 + 255)/256, 256>>>(rel_emb);
    if (outbias)
        bias_out_kernel<<<(TT*TT + 255)/256, 256>>>(rel_emb, outbias);

    // 2) y = film(rmsnorm(x)) -> half
    rmsnorm_film_kernel<<<BT, 256>>>(x, norm1_w, p_g1, p_b1, p_y_h);

    // 3) Q/K/V projections (fp16 MMA)
    dim3 gproj(DD/GBN, BT/GBM);
    gemm_f16_kernel<<<gproj, 256>>>(BT, DD, DD, p_y_h, p_wqT, nullptr, p_q);
    gemm_f16_kernel<<<gproj, 256>>>(BT, DD, DD, p_y_h, p_wkT, nullptr, p_k);
    gemm_f16_kernel<<<gproj, 256>>>(BT, DD, DD, p_y_h, p_wvT, nullptr, p_v);

    // 4) fused flash attention -> half ctx
    flash_attn_kernel<<<dim3(TT/64, BB*HH), 128, sizeof(FlashSmem)>>>(mask);

    // 5) output projection + residual -> x1 (fp32)
    gemm_f16_kernel<<<gproj, 256>>>(BT, DD, DD, p_ctx_h, p_woT, x, p_x1);

    // 6) y2 = film3(rmsnorm(x1)) -> half
    rmsnorm_film_kernel<<<BT, 256>>>(p_x1, norm3_w, p_g3, p_b3, p_y_h);

    // 7) FFN
    gemm_f16_kernel<<<dim3(4*DD/GBN, BT/GBM), 256>>>(BT, 4*DD, DD, p_y_h, p_w1T, nullptr, p_ffn1);
    geglu_kernel<<<(int)(((size_t)BT*2*DD + 255)/256), 256>>>();
    gemm_f16_kernel<<<dim3(DD/GBN, BT/GBM), 256>>>(BT, DD, 2*DD, p_gg_h, p_w2T, p_x1, out);
}

// round 12
// speedup vs baseline: 5.0177x; 1.3055x over previous
#include <cuda_runtime.h>
#include <cuda_fp16.h>
#include <math.h>

#define BB 4
#define TT 1024
#define DD 1024
#define HH 16
#define DHH 64
#define DCC 64
#define BT (BB*TT)        // 4096
#define BTD (BB*TT*DD)    // 4194304
#define BIAS_ELEMS (HH*TT*TT) // 16777216

// ---------------- scratch (device globals; no allocation) ----------------
__device__ float g_gamma1[BB*DD];
__device__ float g_beta1 [BB*DD];
__device__ float g_gamma3[BB*DD];
__device__ float g_beta3 [BB*DD];
__device__ float g_x1  [BTD];
__device__ float g_biasrel[HH*2048];
__device__ float g_ffn1[(size_t)BT*4*DD];
// fp16 activation/weight buffers (GEMM operands)
__device__ __half g_y_h  [BTD];
__device__ __half g_q_h  [BTD];
__device__ __half g_k_h  [BTD];
__device__ __half g_v_h  [BTD];
__device__ __half g_ctx_h[BTD];
__device__ __half g_gg_h [(size_t)BT*2*DD];
__device__ __half g_wqT[DD*DD];
__device__ __half g_wkT[DD*DD];
__device__ __half g_wvT[DD*DD];
__device__ __half g_woT[DD*DD];
__device__ __half g_w1T[(size_t)4*DD*DD];
__device__ __half g_w2T[(size_t)2*DD*DD];

__device__ __forceinline__ unsigned smem_u32(const void* p) {
    return (unsigned)__cvta_generic_to_shared(p);
}

// ---------------- FiLM params ----------------
__global__ void film_params_kernel(const float* __restrict__ cond,
    const float* __restrict__ g1w, const float* __restrict__ g1b,
    const float* __restrict__ b1w, const float* __restrict__ b1b,
    const float* __restrict__ g3w, const float* __restrict__ g3b,
    const float* __restrict__ b3w, const float* __restrict__ b3b)
{
    int idx = blockIdx.x * blockDim.x + threadIdx.x;
    if (idx >= BB*DD) return;
    int b = idx / DD, d = idx % DD;
    float s1 = 0.f, s2 = 0.f, s3 = 0.f, s4 = 0.f;
    #pragma unroll 8
    for (int c = 0; c < DCC; c++) {
        float cv = cond[b*DCC + c];
        s1 += cv * g1w[c*DD + d];
        s2 += cv * b1w[c*DD + d];
        s3 += cv * g3w[c*DD + d];
        s4 += cv * b3w[c*DD + d];
    }
    g_gamma1[idx] = s1 + g1b[d];
    g_beta1 [idx] = s2 + b1b[d];
    g_gamma3[idx] = s3 + g3b[d];
    g_beta3 [idx] = s4 + b3b[d];
}

// ---------------- T5 bucket ----------------
__device__ __forceinline__ int t5_bucket(int rp) {
    int bucket = (rp > 0) ? 16 : 0;
    int arp = rp < 0 ? -rp : rp;
    int off;
    if (arp < 8) {
        off = arp;
    } else {
        float l = logf((float)arp * 0.125f) / logf(16.0f) * 8.0f;
        off = 8 + (int)l;
        if (off > 15) off = 15;
    }
    return bucket + off;
}

__global__ void biasrel_kernel(const float* __restrict__ rel_emb)
{
    int idx = blockIdx.x * blockDim.x + threadIdx.x;
    if (idx >= 2047) return;
    int bucket = t5_bucket(idx - 1023);
    #pragma unroll
    for (int h = 0; h < HH; h++)
        g_biasrel[h*2048 + idx] = rel_emb[bucket*HH + h];
}

__global__ void bias_out_kernel(const float* __restrict__ rel_emb, float* __restrict__ outbias)
{
    int idx = blockIdx.x * blockDim.x + threadIdx.x;
    if (idx >= TT*TT) return;
    int q = idx / TT, k = idx % TT;
    int bucket = t5_bucket(k - q);
    #pragma unroll
    for (int h = 0; h < HH; h++)
        outbias[(size_t)h*TT*TT + idx] = rel_emb[bucket*HH + h];
}

// ---------------- weight transpose -> half K-major: src[K][N] -> dst[N][K] ----------------
__global__ void transpose_h_kernel(const float* __restrict__ src, __half* __restrict__ dst,
                                   int Kd, int Nd)
{
    __shared__ float ts[32][33];
    int n0 = blockIdx.x*32, k0 = blockIdx.y*32;
    int tx = threadIdx.x, ty = threadIdx.y;   // 32 x 8
    #pragma unroll
    for (int i = 0; i < 32; i += 8)
        ts[ty+i][tx] = src[(size_t)(k0+ty+i)*Nd + n0+tx];
    __syncthreads();
    #pragma unroll
    for (int i = 0; i < 32; i += 8)
        dst[(size_t)(n0+ty+i)*Kd + k0+tx] = __float2half_rn(ts[tx][ty+i]);
}

// ---------------- RMSNorm + FiLM (float4 in, half out) ----------------
__global__ void rmsnorm_film_kernel(const float* __restrict__ x, const float* __restrict__ w,
                                    const float* __restrict__ gamma, const float* __restrict__ beta,
                                    __half* __restrict__ y)
{
    int row = blockIdx.x;
    int b = row / TT;
    const float* xr = x + (size_t)row * DD;
    __half* yr = y + (size_t)row * DD;
    int d4 = threadIdx.x * 4;
    float4 v = *reinterpret_cast<const float4*>(&xr[d4]);
    float s = v.x*v.x + v.y*v.y + v.z*v.z + v.w*v.w;
    __shared__ float red[256];
    red[threadIdx.x] = s; __syncthreads();
    for (int o = 128; o > 0; o >>= 1) {
        if (threadIdx.x < o) red[threadIdx.x] += red[threadIdx.x + o];
        __syncthreads();
    }
    float rs = rsqrtf(red[0] * (1.0f/DD) + 1e-6f);
    float4 wv = *reinterpret_cast<const float4*>(&w[d4]);
    float4 gv = *reinterpret_cast<const float4*>(&gamma[b*DD + d4]);
    float4 bv = *reinterpret_cast<const float4*>(&beta[b*DD + d4]);
    __half2 h0 = __floats2half2_rn(wv.x * v.x * rs * (gv.x + 1.0f) + bv.x,
                                   wv.y * v.y * rs * (gv.y + 1.0f) + bv.y);
    __half2 h1 = __floats2half2_rn(wv.z * v.z * rs * (gv.z + 1.0f) + bv.z,
                                   wv.w * v.w * rs * (gv.w + 1.0f) + bv.w);
    *reinterpret_cast<__half2*>(&yr[d4])   = h0;
    *reinterpret_cast<__half2*>(&yr[d4+2]) = h1;
}

// ---------------- FP16 tensor-core GEMM, both operands K-major half ----------------
// C(float) or Ch(half) = A[M,K] @ Bt[N,K]^T (+Res fp32). M,N % 128 == 0, K % 32 == 0.
#define GBM 128
#define GBN 128
#define GBK 32
#define HPAD 8   // halves -> row stride 80 B

__global__ __launch_bounds__(256) void gemm_f16_kernel(int M, int N, int K,
    const __half* __restrict__ A, const __half* __restrict__ Bt,
    const float* __restrict__ Res, float* __restrict__ C, __half* __restrict__ Ch)
{
    __shared__ __half As[2][GBM][GBK+HPAD];
    __shared__ __half Bs[2][GBN][GBK+HPAD];

    int tid = threadIdx.x;
    int wid = tid >> 5, lane = tid & 31;
    int wm = wid >> 2, wn = wid & 3;      // 2 x 4 warps -> warp tile 64 x 32

    const __half* Ag = A  + (size_t)blockIdx.y * GBM * K;
    const __half* Bg = Bt + (size_t)blockIdx.x * GBN * K;

    float acc[4][4][4];
    #pragma unroll
    for (int i = 0; i < 4; i++)
        #pragma unroll
        for (int j = 0; j < 4; j++)
            #pragma unroll
            for (int r = 0; r < 4; r++) acc[i][j][r] = 0.f;

    int lr = tid >> 2, lc = (tid & 3) * 8;

    #define LOAD_STAGE(buf, kt) do { \
        asm volatile("cp.async.cg.shared.global [%0], [%1], 16;\n" \
            :: "r"(smem_u32(&As[buf][lr][lc])),    "l"(Ag + (size_t)lr*K + (kt) + lc)); \
        asm volatile("cp.async.cg.shared.global [%0], [%1], 16;\n" \
            :: "r"(smem_u32(&As[buf][lr+64][lc])), "l"(Ag + (size_t)(lr+64)*K + (kt) + lc)); \
        asm volatile("cp.async.cg.shared.global [%0], [%1], 16;\n" \
            :: "r"(smem_u32(&Bs[buf][lr][lc])),    "l"(Bg + (size_t)lr*K + (kt) + lc)); \
        asm volatile("cp.async.cg.shared.global [%0], [%1], 16;\n" \
            :: "r"(smem_u32(&Bs[buf][lr+64][lc])), "l"(Bg + (size_t)(lr+64)*K + (kt) + lc)); \
        asm volatile("cp.async.commit_group;\n"); \
    } while (0)

    int nk = K / GBK;
    LOAD_STAGE(0, 0);

    for (int t = 0; t < nk; t++) {
        if (t + 1 < nk) LOAD_STAGE((t+1) & 1, (t+1) * GBK);
        else            asm volatile("cp.async.commit_group;\n");
        asm volatile("cp.async.wait_group 1;\n");
        __syncthreads();

        int buf = t & 1;
        #pragma unroll
        for (int kk = 0; kk < 2; kk++) {
            int k0 = kk * 16;
            int kc = k0 + (lane >> 4) * 8;
            unsigned af[4][4];
            unsigned bf[2][4];
            #pragma unroll
            for (int i = 0; i < 4; i++) {
                int m = wm*64 + i*16 + (lane & 15);
                asm volatile("ldmatrix.sync.aligned.m8n8.x4.shared.b16 {%0,%1,%2,%3}, [%4];\n"
                    : "=r"(af[i][0]), "=r"(af[i][1]), "=r"(af[i][2]), "=r"(af[i][3])
                    : "r"(smem_u32(&As[buf][m][kc])));
            }
            #pragma unroll
            for (int jb = 0; jb < 2; jb++) {
                int n = wn*32 + jb*16 + (lane & 15);
                asm volatile("ldmatrix.sync.aligned.m8n8.x4.shared.b16 {%0,%1,%2,%3}, [%4];\n"
                    : "=r"(bf[jb][0]), "=r"(bf[jb][1]), "=r"(bf[jb][2]), "=r"(bf[jb][3])
                    : "r"(smem_u32(&Bs[buf][n][kc])));
            }
            #pragma unroll
            for (int i = 0; i < 4; i++)
                #pragma unroll
                for (int j = 0; j < 4; j++) {
                    int jb = j >> 1, p = j & 1;
                    asm volatile(
                        "mma.sync.aligned.m16n8k16.row.col.f32.f16.f16.f32 "
                        "{%0,%1,%2,%3}, {%4,%5,%6,%7}, {%8,%9}, {%0,%1,%2,%3};\n"
                        : "+f"(acc[i][j][0]), "+f"(acc[i][j][1]), "+f"(acc[i][j][2]), "+f"(acc[i][j][3])
                        : "r"(af[i][0]), "r"(af[i][1]), "r"(af[i][2]), "r"(af[i][3]),
                          "r"(bf[jb][p]), "r"(bf[jb][p+2]));
                }
        }
        __syncthreads();
    }
    #undef LOAD_STAGE

    if (Ch) {
        __half* Cg = Ch + (size_t)blockIdx.y * GBM * N + blockIdx.x * GBN;
        #pragma unroll
        for (int i = 0; i < 4; i++) {
            int r0 = wm*64 + i*16 + (lane >> 2);
            int r1 = r0 + 8;
            #pragma unroll
            for (int j = 0; j < 4; j++) {
                int c0 = wn*32 + j*8 + (lane & 3) * 2;
                *reinterpret_cast<__half2*>(&Cg[(size_t)r0*N + c0]) =
                    __floats2half2_rn(acc[i][j][0], acc[i][j][1]);
                *reinterpret_cast<__half2*>(&Cg[(size_t)r1*N + c0]) =
                    __floats2half2_rn(acc[i][j][2], acc[i][j][3]);
            }
        }
    } else {
        float* Cg = C + (size_t)blockIdx.y * GBM * N + blockIdx.x * GBN;
        const float* Rg = Res ? Res + (size_t)blockIdx.y * GBM * N + blockIdx.x * GBN : nullptr;
        #pragma unroll
        for (int i = 0; i < 4; i++) {
            int r0 = wm*64 + i*16 + (lane >> 2);
            int r1 = r0 + 8;
            #pragma unroll
            for (int j = 0; j < 4; j++) {
                int c0 = wn*32 + j*8 + (lane & 3) * 2;
                float v0 = acc[i][j][0], v1 = acc[i][j][1];
                float v2 = acc[i][j][2], v3 = acc[i][j][3];
                if (Rg) {
                    v0 += Rg[(size_t)r0*N + c0];   v1 += Rg[(size_t)r0*N + c0+1];
                    v2 += Rg[(size_t)r1*N + c0];   v3 += Rg[(size_t)r1*N + c0+1];
                }
                Cg[(size_t)r0*N + c0]   = v0;  Cg[(size_t)r0*N + c0+1] = v1;
                Cg[(size_t)r1*N + c0]   = v2;  Cg[(size_t)r1*N + c0+1] = v3;
            }
        }
    }
}

// ---------------- fused flash attention (fp16 mma k16) ----------------
// grid (T/64, B*H), 128 threads (4 warps x 16 q-rows)
#define FPITCH 72   // half pitch: 144 B rows -> conflict-free ldmatrix

struct FlashSmemH {
    __half Qh[64][FPITCH];
    __half Kh[64][FPITCH];
    __half Vh[64][FPITCH];
    __half Ph[4][16][FPITCH];
    float  Sb[128];
};

__global__ __launch_bounds__(128) void flash_attn_kernel(const int* __restrict__ mask)
{
    __shared__ FlashSmemH S;

    int qt = blockIdx.x, bh = blockIdx.y;
    int b = bh / HH, h = bh % HH;
    int q0 = qt * 64;
    int tid = threadIdx.x, wid = tid >> 5, lane = tid & 31;
    int lq = lane >> 2, lk = lane & 3;
    int qrel = wid*16 + lq;

    // fill Q once, prescaled by 0.125 (exact in half)
    const __half2 qscale = __floats2half2_rn(0.125f, 0.125f);
    for (int i = tid; i < 64*16; i += 128) {
        int r = i >> 4, c4 = (i & 15) * 4;
        size_t off = (size_t)(b*TT + q0 + r)*DD + h*DHH + c4;
        __half2 a0 = *reinterpret_cast<const __half2*>(&g_q_h[off]);
        __half2 a1 = *reinterpret_cast<const __half2*>(&g_q_h[off+2]);
        *reinterpret_cast<__half2*>(&S.Qh[r][c4])   = __hmul2(a0, qscale);
        *reinterpret_cast<__half2*>(&S.Qh[r][c4+2]) = __hmul2(a1, qscale);
    }

    float o[8][4];
    #pragma unroll
    for (int n = 0; n < 8; n++)
        #pragma unroll
        for (int r = 0; r < 4; r++) o[n][r] = 0.f;
    float mrow[2] = { -3.0e38f, -3.0e38f };
    float lrow[2] = { 0.f, 0.f };

    for (int kt0 = 0; kt0 < TT; kt0 += 64) {
        __syncthreads();
        for (int i = tid; i < 64*16; i += 128) {
            int r = i >> 4, c4 = (i & 15) * 4;
            size_t off = (size_t)(b*TT + kt0 + r)*DD + h*DHH + c4;
            *reinterpret_cast<uint2*>(&S.Kh[r][c4]) =
                *reinterpret_cast<const uint2*>(&g_k_h[off]);
            *reinterpret_cast<uint2*>(&S.Vh[r][c4]) =
                *reinterpret_cast<const uint2*>(&g_v_h[off]);
        }
        if (tid < 127) S.Sb[tid] = g_biasrel[h*2048 + (kt0 - q0 + 960) + tid];
        __syncthreads();

        // ---- S = Q @ K^T (fp16 k16) ----
        float sacc[8][4];
        #pragma unroll
        for (int n = 0; n < 8; n++)
            #pragma unroll
            for (int r = 0; r < 4; r++) sacc[n][r] = 0.f;

        #pragma unroll
        for (int ks = 0; ks < 4; ks++) {
            int kc = ks*16 + (lane >> 4) * 8;
            unsigned aq[4];
            asm volatile("ldmatrix.sync.aligned.m8n8.x4.shared.b16 {%0,%1,%2,%3}, [%4];\n"
                : "=r"(aq[0]), "=r"(aq[1]), "=r"(aq[2]), "=r"(aq[3])
                : "r"(smem_u32(&S.Qh[wid*16 + (lane & 15)][kc])));
            unsigned bk[4][4];
            #pragma unroll
            for (int jb = 0; jb < 4; jb++) {
                asm volatile("ldmatrix.sync.aligned.m8n8.x4.shared.b16 {%0,%1,%2,%3}, [%4];\n"
                    : "=r"(bk[jb][0]), "=r"(bk[jb][1]), "=r"(bk[jb][2]), "=r"(bk[jb][3])
                    : "r"(smem_u32(&S.Kh[jb*16 + (lane & 15)][kc])));
            }
            #pragma unroll
            for (int n8 = 0; n8 < 8; n8++) {
                int jb = n8 >> 1, p = n8 & 1;
                asm volatile(
                    "mma.sync.aligned.m16n8k16.row.col.f32.f16.f16.f32 "
                    "{%0,%1,%2,%3}, {%4,%5,%6,%7}, {%8,%9}, {%0,%1,%2,%3};\n"
                    : "+f"(sacc[n8][0]), "+f"(sacc[n8][1]), "+f"(sacc[n8][2]), "+f"(sacc[n8][3])
                    : "r"(aq[0]), "r"(aq[1]), "r"(aq[2]), "r"(aq[3]),
                      "r"(bk[jb][p]), "r"(bk[jb][p+2]));
            }
        }

        // ---- bias + mask + online softmax (fp32) ----
        float mnew[2] = { mrow[0], mrow[1] };
        #pragma unroll
        for (int n = 0; n < 8; n++) {
            #pragma unroll
            for (int e = 0; e < 2; e++) {
                int qr = qrel + e*8;
                const int* mrowp = mask + ((size_t)(b*TT + q0 + qr))*TT + kt0;
                #pragma unroll
                for (int c = 0; c < 2; c++) {
                    int kr = n*8 + 2*lk + c;
                    float s = sacc[n][e*2+c] + S.Sb[kr - qr + 63];
                    if (mrowp[kr] == 0) s = -1e9f;
                    sacc[n][e*2+c] = s;
                    mnew[e] = fmaxf(mnew[e], s);
                }
            }
        }
        #pragma unroll
        for (int e = 0; e < 2; e++) {
            mnew[e] = fmaxf(mnew[e], __shfl_xor_sync(0xffffffffu, mnew[e], 1));
            mnew[e] = fmaxf(mnew[e], __shfl_xor_sync(0xffffffffu, mnew[e], 2));
        }
        float alpha[2], rs[2] = {0.f, 0.f};
        alpha[0] = __expf(mrow[0] - mnew[0]);
        alpha[1] = __expf(mrow[1] - mnew[1]);
        mrow[0] = mnew[0]; mrow[1] = mnew[1];

        #pragma unroll
        for (int n = 0; n < 8; n++) {
            #pragma unroll
            for (int e = 0; e < 2; e++) {
                float p0 = __expf(sacc[n][e*2+0] - mnew[e]);
                float p1 = __expf(sacc[n][e*2+1] - mnew[e]);
                rs[e] += p0 + p1;
                *reinterpret_cast<__half2*>(&S.Ph[wid][lq + e*8][n*8 + 2*lk]) =
                    __floats2half2_rn(p0, p1);
            }
        }
        #pragma unroll
        for (int e = 0; e < 2; e++) {
            rs[e] += __shfl_xor_sync(0xffffffffu, rs[e], 1);
            rs[e] += __shfl_xor_sync(0xffffffffu, rs[e], 2);
            lrow[e] = lrow[e] * alpha[e] + rs[e];
        }
        #pragma unroll
        for (int n = 0; n < 8; n++) {
            o[n][0] *= alpha[0]; o[n][1] *= alpha[0];
            o[n][2] *= alpha[1]; o[n][3] *= alpha[1];
        }
        __syncwarp();

        // ---- O += P @ V (fp16 k16; V via ldmatrix.trans) ----
        #pragma unroll
        for (int ks = 0; ks < 4; ks++) {
            int kc = ks*16 + (lane >> 4) * 8;
            unsigned ap[4];
            asm volatile("ldmatrix.sync.aligned.m8n8.x4.shared.b16 {%0,%1,%2,%3}, [%4];\n"
                : "=r"(ap[0]), "=r"(ap[1]), "=r"(ap[2]), "=r"(ap[3])
                : "r"(smem_u32(&S.Ph[wid][lane & 15][kc])));
            int vrow = ks*16 + (lane & 7) + ((lane >> 3) & 1) * 8;
            unsigned bv[4][4];
            #pragma unroll
            for (int jb = 0; jb < 4; jb++) {
                int vcol = jb*16 + ((lane >> 4) & 1) * 8;
                asm volatile("ldmatrix.sync.aligned.m8n8.x4.trans.shared.b16 {%0,%1,%2,%3}, [%4];\n"
                    : "=r"(bv[jb][0]), "=r"(bv[jb][1]), "=r"(bv[jb][2]), "=r"(bv[jb][3])
                    : "r"(smem_u32(&S.Vh[vrow][vcol])));
            }
            #pragma unroll
            for (int n8 = 0; n8 < 8; n8++) {
                int jb = n8 >> 1, q2 = n8 & 1;
                asm volatile(
                    "mma.sync.aligned.m16n8k16.row.col.f32.f16.f16.f32 "
                    "{%0,%1,%2,%3}, {%4,%5,%6,%7}, {%8,%9}, {%0,%1,%2,%3};\n"
                    : "+f"(o[n8][0]), "+f"(o[n8][1]), "+f"(o[n8][2]), "+f"(o[n8][3])
                    : "r"(ap[0]), "r"(ap[1]), "r"(ap[2]), "r"(ap[3]),
                      "r"(bv[jb][2*q2]), "r"(bv[jb][2*q2+1]));
            }
        }
        __syncwarp();
    }

    // ---- epilogue: O /= l -> half ctx ----
    float inv0 = 1.0f / lrow[0], inv1 = 1.0f / lrow[1];
    #pragma unroll
    for (int e = 0; e < 2; e++) {
        int qg = b*TT + q0 + qrel + e*8;
        float inv = e ? inv1 : inv0;
        #pragma unroll
        for (int n = 0; n < 8; n++) {
            __half2 hw = __floats2half2_rn(o[n][e*2+0] * inv, o[n][e*2+1] * inv);
            *reinterpret_cast<__half2*>(&g_ctx_h[(size_t)qg*DD + h*DHH + n*8 + 2*lk]) = hw;
        }
    }
}

// ---------------- GEGLU (half output) ----------------
__global__ void geglu_kernel()
{
    size_t idx = (size_t)blockIdx.x * blockDim.x + threadIdx.x;
    if (idx >= (size_t)BT * 2 * DD) return;
    size_t r = idx / (2*DD);
    int c = (int)(idx % (2*DD));
    float p1 = g_ffn1[r * 4*DD + c];
    float p2 = g_ffn1[r * 4*DD + 2*DD + c];
    float gelu = 0.5f * p2 * (1.0f + erff(p2 * 0.70710678118654752f));
    g_gg_h[idx] = __float2half_rn(p1 * gelu);
}

// ---------------- host launcher ----------------
extern "C" void kernel_launch(void* const* d_in, const int* in_sizes, int n_in,
                              void* d_out, int out_size)
{
    const float* x       = (const float*)d_in[0];
    const int*   mask    = (const int*)  d_in[1];
    const float* cond    = (const float*)d_in[2];
    const float* norm1_w = (const float*)d_in[3];
    const float* f1gw    = (const float*)d_in[4];
    const float* f1gb    = (const float*)d_in[5];
    const float* f1bw    = (const float*)d_in[6];
    const float* f1bb    = (const float*)d_in[7];
    const float* wq      = (const float*)d_in[8];
    const float* wk      = (const float*)d_in[9];
    const float* wv      = (const float*)d_in[10];
    const float* wo      = (const float*)d_in[11];
    const float* rel_emb = (const float*)d_in[12];
    const float* norm3_w = (const float*)d_in[13];
    const float* f3gw    = (const float*)d_in[14];
    const float* f3gb    = (const float*)d_in[15];
    const float* f3bw    = (const float*)d_in[16];
    const float* f3bb    = (const float*)d_in[17];
    const float* w1      = (const float*)d_in[18];
    const float* w2      = (const float*)d_in[19];
    float* out = (float*)d_out;
    float* outbias = (out_size >= BTD + BIAS_ELEMS) ? out + BTD : nullptr;

    float *p_x1, *p_ffn1;
    float *p_g1, *p_b1, *p_g3, *p_b3;
    __half *p_y_h, *p_q_h, *p_k_h, *p_v_h, *p_ctx_h, *p_gg_h;
    __half *p_wqT, *p_wkT, *p_wvT, *p_woT, *p_w1T, *p_w2T;
    cudaGetSymbolAddress((void**)&p_g1, g_gamma1);
    cudaGetSymbolAddress((void**)&p_b1, g_beta1);
    cudaGetSymbolAddress((void**)&p_g3, g_gamma3);
    cudaGetSymbolAddress((void**)&p_b3, g_beta3);
    cudaGetSymbolAddress((void**)&p_x1, g_x1);
    cudaGetSymbolAddress((void**)&p_ffn1, g_ffn1);
    cudaGetSymbolAddress((void**)&p_y_h,  g_y_h);
    cudaGetSymbolAddress((void**)&p_q_h,  g_q_h);
    cudaGetSymbolAddress((void**)&p_k_h,  g_k_h);
    cudaGetSymbolAddress((void**)&p_v_h,  g_v_h);
    cudaGetSymbolAddress((void**)&p_ctx_h, g_ctx_h);
    cudaGetSymbolAddress((void**)&p_gg_h, g_gg_h);
    cudaGetSymbolAddress((void**)&p_wqT, g_wqT);
    cudaGetSymbolAddress((void**)&p_wkT, g_wkT);
    cudaGetSymbolAddress((void**)&p_wvT, g_wvT);
    cudaGetSymbolAddress((void**)&p_woT, g_woT);
    cudaGetSymbolAddress((void**)&p_w1T, g_w1T);
    cudaGetSymbolAddress((void**)&p_w2T, g_w2T);

    // 0) transpose weights -> half K-major
    dim3 tb(32, 8);
    transpose_h_kernel<<<dim3(DD/32, DD/32), tb>>>(wq, p_wqT, DD, DD);
    transpose_h_kernel<<<dim3(DD/32, DD/32), tb>>>(wk, p_wkT, DD, DD);
    transpose_h_kernel<<<dim3(DD/32, DD/32), tb>>>(wv, p_wvT, DD, DD);
    transpose_h_kernel<<<dim3(DD/32, DD/32), tb>>>(wo, p_woT, DD, DD);
    transpose_h_kernel<<<dim3(4*DD/32, DD/32), tb>>>(w1, p_w1T, DD, 4*DD);
    transpose_h_kernel<<<dim3(DD/32, 2*DD/32), tb>>>(w2, p_w2T, 2*DD, DD);

    // 1) FiLM params + bias LUT + bias output
    film_params_kernel<<<(BB*DD + 255)/256, 256>>>(cond, f1gw, f1gb, f1bw, f1bb,
                                                   f3gw, f3gb, f3bw, f3bb);
    biasrel_kernel<<<(2047 + 255)/256, 256>>>(rel_emb);
    if (outbias)
        bias_out_kernel<<<(TT*TT + 255)/256, 256>>>(rel_emb, outbias);

    // 2) y = film(rmsnorm(x)) -> half
    rmsnorm_film_kernel<<<BT, 256>>>(x, norm1_w, p_g1, p_b1, p_y_h);

    // 3) Q/K/V projections (fp16 MMA, half output)
    dim3 gproj(DD/GBN, BT/GBM);
    gemm_f16_kernel<<<gproj, 256>>>(BT, DD, DD, p_y_h, p_wqT, nullptr, nullptr, p_q_h);
    gemm_f16_kernel<<<gproj, 256>>>(BT, DD, DD, p_y_h, p_wkT, nullptr, nullptr, p_k_h);
    gemm_f16_kernel<<<gproj, 256>>>(BT, DD, DD, p_y_h, p_wvT, nullptr, nullptr, p_v_h);

    // 4) fused flash attention (fp16) -> half ctx
    flash_attn_kernel<<<dim3(TT/64, BB*HH), 128>>>(mask);

    // 5) output projection + residual -> x1 (fp32)
    gemm_f16_kernel<<<gproj, 256>>>(BT, DD, DD, p_ctx_h, p_woT, x, p_x1, nullptr);

    // 6) y2 = film3(rmsnorm(x1)) -> half
    rmsnorm_film_kernel<<<BT, 256>>>(p_x1, norm3_w, p_g3, p_b3, p_y_h);

    // 7) FFN
    gemm_f16_kernel<<<dim3(4*DD/GBN, BT/GBM), 256>>>(BT, 4*DD, DD, p_y_h, p_w1T, nullptr, p_ffn1, nullptr);
    geglu_kernel<<<(int)(((size_t)BT*2*DD + 255)/256), 256>>>();
    gemm_f16_kernel<<<dim3(DD/GBN, BT/GBM), 256>>>(BT, DD, 2*DD, p_gg_h, p_w2T, p_x1, out, nullptr);
}